// round 2
// baseline (speedup 1.0000x reference)
#include <cuda_runtime.h>
#include <cuda_bf16.h>

// Problem constants
constexpr int NN = 100000;   // N_REQ == N_CODE
constexpr int CC = 256;      // C_OUT == C_IN
constexpr int HH = 8;        // heads
constexpr int EE = 500000;   // edges per type
constexpr int EL = 200000;   // label edges

// ---------------- device scratch (static, no allocations) ----------------
__device__ __align__(16) float    g_h[2][NN * CC];        // projected features: 0=req 1=code
__device__ __align__(16) float    g_out[2][NN * CC];      // aggregated: 0=req 1=code
__device__ __align__(16) float    g_a[4][NN * HH];        // 0:src_rc(req) 1:dst_rc(code) 2:src_cr(code) 3:dst_cr(req)
__device__ __align__(16) unsigned g_mkey[2][NN * HH];     // encoded max keys: 0 for rc(dst=code), 1 for cr(dst=req)
__device__ __align__(16) float    g_ssum[2][NN * HH];     // softmax denominators
__device__ __align__(16) float    g_alpha[2][EE * HH];    // per-edge logits -> exp values
__device__ __align__(16) float    g_bnstat[2][2 * CC];    // [type][sum(256), sumsq(256)]
__device__ __align__(16) float    g_scale[2][CC];
__device__ __align__(16) float    g_shift[2][CC];

// ---------------- kernels ----------------

__global__ void zero_kernel(float4* p, int n4) {
    int i = blockIdx.x * blockDim.x + threadIdx.x;
    int stride = gridDim.x * blockDim.x;
    float4 z = make_float4(0.f, 0.f, 0.f, 0.f);
    for (; i < n4; i += stride) p[i] = z;
}

// H[n,o] = sum_k X[n,k] * W[o,k] + B[o]; K = O = 256.
// 128x64 tile, 256 threads, 8x4 micro-tile per thread. blockIdx.z selects type.
__global__ void gemm_bias_kernel(
    const float* __restrict__ x0, const float* __restrict__ x1,
    const float* __restrict__ w0, const float* __restrict__ w1,
    const float* __restrict__ b0, const float* __restrict__ b1,
    float* __restrict__ h0, float* __restrict__ h1)
{
    const float* X = blockIdx.z ? x1 : x0;
    const float* W = blockIdx.z ? w1 : w0;
    const float* B = blockIdx.z ? b1 : b0;
    float* Hout    = blockIdx.z ? h1 : h0;

    __shared__ float sX[16][128 + 4];
    __shared__ float sW[16][64 + 4];

    int bn = blockIdx.x * 128;
    int bo = blockIdx.y * 64;
    int tid = threadIdx.x;
    int tx = tid & 15;   // o-group: tx*4
    int ty = tid >> 4;   // n-group: ty*8

    float acc[8][4];
#pragma unroll
    for (int i = 0; i < 8; i++)
#pragma unroll
        for (int j = 0; j < 4; j++) acc[i][j] = 0.f;

    for (int k0 = 0; k0 < 256; k0 += 16) {
        // load X tile 128x16 (2048 elems, 8 per thread as 2x float4)
#pragma unroll
        for (int it = 0; it < 2; it++) {
            int idx = tid * 4 + it * 1024;
            int n = idx >> 4, k = idx & 15;
            float4 v = make_float4(0.f, 0.f, 0.f, 0.f);
            if (bn + n < NN) v = *(const float4*)&X[(size_t)(bn + n) * 256 + k0 + k];
            sX[k + 0][n] = v.x; sX[k + 1][n] = v.y; sX[k + 2][n] = v.z; sX[k + 3][n] = v.w;
        }
        // load W tile 64x16 (1024 elems, 4 per thread)
        {
            int idx = tid * 4;
            int o = idx >> 4, k = idx & 15;
            float4 v = *(const float4*)&W[(size_t)(bo + o) * 256 + k0 + k];
            sW[k + 0][o] = v.x; sW[k + 1][o] = v.y; sW[k + 2][o] = v.z; sW[k + 3][o] = v.w;
        }
        __syncthreads();
#pragma unroll
        for (int k = 0; k < 16; k++) {
            float xr[8], wr[4];
#pragma unroll
            for (int i = 0; i < 8; i++) xr[i] = sX[k][ty * 8 + i];
#pragma unroll
            for (int j = 0; j < 4; j++) wr[j] = sW[k][tx * 4 + j];
#pragma unroll
            for (int i = 0; i < 8; i++)
#pragma unroll
                for (int j = 0; j < 4; j++) acc[i][j] += xr[i] * wr[j];
        }
        __syncthreads();
    }
#pragma unroll
    for (int i = 0; i < 8; i++) {
        int n = bn + ty * 8 + i;
        if (n < NN) {
            float4 r;
            r.x = acc[i][0] + B[bo + tx * 4 + 0];
            r.y = acc[i][1] + B[bo + tx * 4 + 1];
            r.z = acc[i][2] + B[bo + tx * 4 + 2];
            r.w = acc[i][3] + B[bo + tx * 4 + 3];
            *(float4*)&Hout[(size_t)n * 256 + bo + tx * 4] = r;
        }
    }
}

// a[n,h] = sum_d h[n, h*32+d] * att[h*32+d], two att vectors per node type.
// one warp per node.
__global__ void node_att_kernel(
    const float* __restrict__ h,
    const float* __restrict__ att1, const float* __restrict__ att2,
    float* __restrict__ a1, float* __restrict__ a2)
{
    int warp = (blockIdx.x * blockDim.x + threadIdx.x) >> 5;
    int lane = threadIdx.x & 31;
    if (warp >= NN) return;
    const float* hr = h + (size_t)warp * 256;
#pragma unroll
    for (int j = 0; j < 8; j++) {
        float v = hr[j * 32 + lane];
        float s1 = v * att1[j * 32 + lane];
        float s2 = v * att2[j * 32 + lane];
#pragma unroll
        for (int o = 16; o; o >>= 1) {
            s1 += __shfl_down_sync(0xFFFFFFFFu, s1, o);
            s2 += __shfl_down_sync(0xFFFFFFFFu, s2, o);
        }
        if (lane == 0) { a1[warp * 8 + j] = s1; a2[warp * 8 + j] = s2; }
    }
}

// Pass 1: per-(edge,head) leaky-relu logit; atomicMax of monotonic key per (dst,head).
__global__ void edge_logits_kernel(
    const int* __restrict__ src_idx, const int* __restrict__ dst_idx,
    const float* __restrict__ a_s, const float* __restrict__ a_d,
    float* __restrict__ alpha, unsigned* __restrict__ mkey)
{
    int t = blockIdx.x * blockDim.x + threadIdx.x;
    if (t >= EE * HH) return;
    int e = t >> 3, h = t & 7;
    int s = src_idx[e], d = dst_idx[e];
    float v = a_s[s * 8 + h] + a_d[d * 8 + h];
    v = v > 0.f ? v : 0.2f * v;
    alpha[t] = v;
    unsigned u = __float_as_uint(v);
    unsigned key = (u & 0x80000000u) ? ~u : (u | 0x80000000u);
    atomicMax(&mkey[d * 8 + h], key);
}

// Pass 2: e = exp(alpha - max); accumulate denominators.
__global__ void edge_exp_kernel(
    const int* __restrict__ dst_idx,
    float* __restrict__ alpha,
    const unsigned* __restrict__ mkey,
    float* __restrict__ ssum)
{
    int t = blockIdx.x * blockDim.x + threadIdx.x;
    if (t >= EE * HH) return;
    int e = t >> 3, h = t & 7;
    int d = dst_idx[e];
    unsigned key = mkey[d * 8 + h];
    float m = (key & 0x80000000u) ? __uint_as_float(key ^ 0x80000000u)
                                  : __uint_as_float(~key);
    float ev = __expf(alpha[t] - m);
    alpha[t] = ev;
    atomicAdd(&ssum[d * 8 + h], ev);
}

// Pass 3: out[dst] += h_src[src] * alpha/(sum+1e-16). 64 threads per edge, float4 atomics.
__global__ void edge_agg_kernel(
    const int* __restrict__ src_idx, const int* __restrict__ dst_idx,
    const float* __restrict__ ev, const float* __restrict__ ssum,
    const float* __restrict__ hsrc, float* __restrict__ out)
{
    __shared__ float w[4][8];
    int sub = threadIdx.x >> 6;
    int lane = threadIdx.x & 63;
    int e = blockIdx.x * 4 + sub;
    int s = 0, d = 0;
    if (e < EE) {
        s = src_idx[e]; d = dst_idx[e];
        if (lane < 8) w[sub][lane] = ev[e * 8 + lane] / (ssum[d * 8 + lane] + 1e-16f);
    }
    __syncthreads();
    if (e >= EE) return;
    float wv = w[sub][lane >> 3];
    float4 v = *(const float4*)&hsrc[(size_t)s * 256 + lane * 4];
    float4 r = make_float4(v.x * wv, v.y * wv, v.z * wv, v.w * wv);
    atomicAdd((float4*)&out[(size_t)d * 256 + lane * 4], r);
}

// BN stats: per-column sum / sumsq of relu(out) over row chunks.
__global__ void bn_stats_kernel(const float* __restrict__ out, float* __restrict__ stat,
                                int rows_per_block)
{
    int c = threadIdx.x;
    int r0 = blockIdx.x * rows_per_block;
    int r1 = min(r0 + rows_per_block, NN);
    float s = 0.f, q = 0.f;
    for (int r = r0; r < r1; r++) {
        float v = fmaxf(out[(size_t)r * 256 + c], 0.f);
        s += v; q += v * v;
    }
    atomicAdd(&stat[c], s);
    atomicAdd(&stat[256 + c], q);
}

__global__ void bn_finalize_kernel(const float* __restrict__ stat,
                                   const float* __restrict__ gamma,
                                   const float* __restrict__ beta,
                                   float* __restrict__ scale, float* __restrict__ shift)
{
    int c = threadIdx.x;
    const float inv = 1.f / (float)NN;
    float mu = stat[c] * inv;
    float var = stat[256 + c] * inv - mu * mu;
    float sc = gamma[c] * rsqrtf(var + 1e-5f);
    scale[c] = sc;
    shift[c] = beta[c] - mu * sc;
}

// Final: per label edge dot of normalized features, sigmoid. One warp per edge.
__global__ void edge_predict_kernel(
    const int* __restrict__ li, const int* __restrict__ lj,
    const float* __restrict__ outr, const float* __restrict__ outc,
    const float* __restrict__ scale_r, const float* __restrict__ shift_r,
    const float* __restrict__ scale_c, const float* __restrict__ shift_c,
    float* __restrict__ y)
{
    int warp = (blockIdx.x * blockDim.x + threadIdx.x) >> 5;
    int lane = threadIdx.x & 31;
    if (warp >= EL) return;
    int i = li[warp], j = lj[warp];
    float acc = 0.f;
#pragma unroll
    for (int jj = 0; jj < 8; jj++) {
        int c = lane + 32 * jj;
        float zr = fmaxf(outr[(size_t)i * 256 + c], 0.f) * scale_r[c] + shift_r[c];
        float zc = fmaxf(outc[(size_t)j * 256 + c], 0.f) * scale_c[c] + shift_c[c];
        acc += zr * zc;
    }
#pragma unroll
    for (int o = 16; o; o >>= 1) acc += __shfl_down_sync(0xFFFFFFFFu, acc, o);
    if (lane == 0) y[warp] = 1.f / (1.f + __expf(-acc));
}

// ---------------- host launch ----------------

extern "C" void kernel_launch(void* const* d_in, const int* in_sizes, int n_in,
                              void* d_out, int out_size)
{
    const float* x_req   = (const float*)d_in[0];
    const float* x_code  = (const float*)d_in[1];
    const int*   ei_rc   = (const int*)d_in[2];
    const int*   ei_cr   = (const int*)d_in[3];
    const int*   eli     = (const int*)d_in[4];
    const float* W_req   = (const float*)d_in[5];
    const float* b_req   = (const float*)d_in[6];
    const float* W_code  = (const float*)d_in[7];
    const float* b_code  = (const float*)d_in[8];
    const float* att_src_rc = (const float*)d_in[9];
    const float* att_dst_rc = (const float*)d_in[10];
    const float* att_src_cr = (const float*)d_in[11];
    const float* att_dst_cr = (const float*)d_in[12];
    // d_in[13..15]: k_W, k_b, q -> mathematically identity here (softmax over M=1)
    const float* gamma = (const float*)d_in[16];
    const float* beta  = (const float*)d_in[17];
    float* y = (float*)d_out;

    float *h_base, *out_base, *a_base, *ssum_base, *alpha_base, *bn_base, *scale_base, *shift_base;
    unsigned* mkey_base;
    cudaGetSymbolAddress((void**)&h_base, g_h);
    cudaGetSymbolAddress((void**)&out_base, g_out);
    cudaGetSymbolAddress((void**)&a_base, g_a);
    cudaGetSymbolAddress((void**)&mkey_base, g_mkey);
    cudaGetSymbolAddress((void**)&ssum_base, g_ssum);
    cudaGetSymbolAddress((void**)&alpha_base, g_alpha);
    cudaGetSymbolAddress((void**)&bn_base, g_bnstat);
    cudaGetSymbolAddress((void**)&scale_base, g_scale);
    cudaGetSymbolAddress((void**)&shift_base, g_shift);

    float* h_req  = h_base;
    float* h_code = h_base + (size_t)NN * CC;
    float* out_req  = out_base;
    float* out_code = out_base + (size_t)NN * CC;
    float* a_src_rc = a_base + 0 * (size_t)NN * HH;
    float* a_dst_rc = a_base + 1 * (size_t)NN * HH;
    float* a_src_cr = a_base + 2 * (size_t)NN * HH;
    float* a_dst_cr = a_base + 3 * (size_t)NN * HH;
    unsigned* mkey_code = mkey_base;                    // rc: dst = code
    unsigned* mkey_req  = mkey_base + (size_t)NN * HH;  // cr: dst = req
    float* ssum_code = ssum_base;
    float* ssum_req  = ssum_base + (size_t)NN * HH;
    float* alpha_rc = alpha_base;
    float* alpha_cr = alpha_base + (size_t)EE * HH;
    float* bn_req  = bn_base;
    float* bn_code = bn_base + 2 * CC;
    float* scale_req  = scale_base;
    float* scale_code = scale_base + CC;
    float* shift_req  = shift_base;
    float* shift_code = shift_base + CC;

    const int* src_rc = ei_rc;          const int* dst_rc = ei_rc + EE;
    const int* src_cr = ei_cr;          const int* dst_cr = ei_cr + EE;
    const int* li = eli;                const int* lj = eli + EL;

    // ---- zero scratch (graph-replayed every run) ----
    zero_kernel<<<2048, 256>>>((float4*)out_base, (2 * NN * CC) / 4);
    zero_kernel<<<512, 256>>>((float4*)mkey_base, (2 * NN * HH) / 4);
    zero_kernel<<<512, 256>>>((float4*)ssum_base, (2 * NN * HH) / 4);
    zero_kernel<<<1, 256>>>((float4*)bn_base, (2 * 2 * CC) / 4);

    // ---- projections: h = x @ W^T + b ----
    gemm_bias_kernel<<<dim3((NN + 127) / 128, 4, 2), 256>>>(
        x_req, x_code, W_req, W_code, b_req, b_code, h_req, h_code);

    // ---- per-node attention scalars ----
    node_att_kernel<<<(NN * 32 + 255) / 256, 256>>>(h_req, att_src_rc, att_dst_cr, a_src_rc, a_dst_cr);
    node_att_kernel<<<(NN * 32 + 255) / 256, 256>>>(h_code, att_dst_rc, att_src_cr, a_dst_rc, a_src_cr);

    // ---- edge softmax pass 1: logits + segment max ----
    int eblk = (EE * HH + 255) / 256;
    edge_logits_kernel<<<eblk, 256>>>(src_rc, dst_rc, a_src_rc, a_dst_rc, alpha_rc, mkey_code);
    edge_logits_kernel<<<eblk, 256>>>(src_cr, dst_cr, a_src_cr, a_dst_cr, alpha_cr, mkey_req);

    // ---- pass 2: exp + segment sum ----
    edge_exp_kernel<<<eblk, 256>>>(dst_rc, alpha_rc, mkey_code, ssum_code);
    edge_exp_kernel<<<eblk, 256>>>(dst_cr, alpha_cr, mkey_req, ssum_req);

    // ---- pass 3: weighted aggregation ----
    edge_agg_kernel<<<EE / 4, 256>>>(src_rc, dst_rc, alpha_rc, ssum_code, h_req, out_code);
    edge_agg_kernel<<<EE / 4, 256>>>(src_cr, dst_cr, alpha_cr, ssum_req, h_code, out_req);

    // ---- batchnorm (relu fused at read) ----
    int rpb = (NN + 511) / 512;
    bn_stats_kernel<<<512, 256>>>(out_req, bn_req, rpb);
    bn_stats_kernel<<<512, 256>>>(out_code, bn_code, rpb);
    bn_finalize_kernel<<<1, 256>>>(bn_req, gamma, beta, scale_req, shift_req);
    bn_finalize_kernel<<<1, 256>>>(bn_code, gamma, beta, scale_code, shift_code);

    // ---- edge classifier ----
    edge_predict_kernel<<<(EL * 32 + 255) / 256, 256>>>(
        li, lj, out_req, out_code, scale_req, shift_req, scale_code, shift_code, y);
}

// round 8
// speedup vs baseline: 1.4721x; 1.4721x over previous
#include <cuda_runtime.h>
#include <cuda_bf16.h>
#include <cuda_fp16.h>
#include <cstdint>

// Problem constants
constexpr int NN = 100000;   // N_REQ == N_CODE
constexpr int CC = 256;      // C_OUT == C_IN
constexpr int HH = 8;        // heads
constexpr int EE = 500000;   // edges per type
constexpr int EL = 200000;   // label edges

// ---------------- device scratch (static, no allocations) ----------------
__device__ __align__(16) __half    g_h[2][NN * CC];       // projected features (fp16)
__device__ __align__(16) float     g_out[2][NN * CC];     // aggregated
__device__ __align__(16) float     g_a[4][NN * HH];       // attention scalars
__device__ __align__(16) unsigned  g_mkey[2][NN * HH];    // softmax max keys
__device__ __align__(16) float     g_ssum[2][NN * HH];    // softmax denominators
__device__ __align__(16) float     g_alpha[2][EE * HH];   // per-edge logits/exp
__device__ __align__(16) float     g_bnstat[2][2 * CC];
__device__ __align__(16) float     g_scale[2][CC];
__device__ __align__(16) float     g_shift[2][CC];
// bf16 hi/lo split buffers for tensor-core GEMM
__device__ __align__(16) __nv_bfloat16 g_xhi[2][NN * CC];
__device__ __align__(16) __nv_bfloat16 g_xlo[2][NN * CC];
__device__ __align__(16) __nv_bfloat16 g_whi[2][CC * CC];
__device__ __align__(16) __nv_bfloat16 g_wlo[2][CC * CC];

// ---------------- PTX helpers (plain sm_80+ features only) ----------------
__device__ __forceinline__ uint32_t smem_to_u32(const void* p) {
    uint32_t a;
    asm("{ .reg .u64 t; cvta.to.shared.u64 t, %1; cvt.u32.u64 %0, t; }" : "=r"(a) : "l"(p));
    return a;
}
#define SMEM_SWIZZLE_128B(o) ((o) ^ (((o) >> 3) & 0x70))

__device__ __forceinline__ void cp16g(uint32_t dst, const void* src) {
    asm volatile("cp.async.cg.shared.global [%0], [%1], 16;" :: "r"(dst), "l"(src));
}
#define CP_COMMIT() asm volatile("cp.async.commit_group;" ::: "memory")
#define CP_WAIT1()  asm volatile("cp.async.wait_group 1;" ::: "memory")
#define CP_WAIT0()  asm volatile("cp.async.wait_group 0;" ::: "memory")

__device__ __forceinline__ void ldsm4(uint32_t* r, uint32_t addr) {
    asm volatile("ldmatrix.sync.aligned.m8n8.x4.shared.b16 {%0,%1,%2,%3}, [%4];"
        : "=r"(r[0]), "=r"(r[1]), "=r"(r[2]), "=r"(r[3]) : "r"(addr));
}

__device__ __forceinline__ void mma_bf16(float* c, const uint32_t* a, uint32_t b0, uint32_t b1) {
    asm volatile("mma.sync.aligned.m16n8k16.row.col.f32.bf16.bf16.f32 "
        "{%0,%1,%2,%3}, {%4,%5,%6,%7}, {%8,%9}, {%0,%1,%2,%3};"
        : "+f"(c[0]), "+f"(c[1]), "+f"(c[2]), "+f"(c[3])
        : "r"(a[0]), "r"(a[1]), "r"(a[2]), "r"(a[3]), "r"(b0), "r"(b1));
}

// ---------------- kernels ----------------

__global__ void zero_kernel(float4* p, int n4) {
    int i = blockIdx.x * blockDim.x + threadIdx.x;
    int stride = gridDim.x * blockDim.x;
    float4 z = make_float4(0.f, 0.f, 0.f, 0.f);
    for (; i < n4; i += stride) p[i] = z;
}

// split fp32 -> bf16 hi + bf16 lo (exact residual split)
__global__ void split_kernel(const float4* __restrict__ x,
                             uint2* __restrict__ hi, uint2* __restrict__ lo, int n4) {
    int i = blockIdx.x * blockDim.x + threadIdx.x;
    if (i >= n4) return;
    float4 v = x[i];
    __nv_bfloat16 h0 = __float2bfloat16(v.x), h1 = __float2bfloat16(v.y);
    __nv_bfloat16 h2 = __float2bfloat16(v.z), h3 = __float2bfloat16(v.w);
    __nv_bfloat16 l0 = __float2bfloat16(v.x - __bfloat162float(h0));
    __nv_bfloat16 l1 = __float2bfloat16(v.y - __bfloat162float(h1));
    __nv_bfloat16 l2 = __float2bfloat16(v.z - __bfloat162float(h2));
    __nv_bfloat16 l3 = __float2bfloat16(v.w - __bfloat162float(h3));
    uint2 H, L;
    H.x = ((uint32_t)__bfloat16_as_ushort(h1) << 16) | __bfloat16_as_ushort(h0);
    H.y = ((uint32_t)__bfloat16_as_ushort(h3) << 16) | __bfloat16_as_ushort(h2);
    L.x = ((uint32_t)__bfloat16_as_ushort(l1) << 16) | __bfloat16_as_ushort(l0);
    L.y = ((uint32_t)__bfloat16_as_ushort(l3) << 16) | __bfloat16_as_ushort(l2);
    hi[i] = H;
    lo[i] = L;
}

// HMMA GEMM: H[M,N=256] = Xhi*Whi^T + Xhi*Wlo^T + Xlo*Whi^T + bias.
// CTA: 128(M) x 128(N) tile (blockIdx.y picks N half), 8 warps of 64x32.
// 12 K-chunks of 64 (3 pieces x 4), cp.async double-buffered, ldmatrix + mma.
// Fused epilogue: store h as fp16, per-head attention dots (one head per warp).
__global__ void __launch_bounds__(256, 2) mma_gemm_kernel(
    const __nv_bfloat16* __restrict__ xhi, const __nv_bfloat16* __restrict__ xlo,
    const __nv_bfloat16* __restrict__ whi, const __nv_bfloat16* __restrict__ wlo,
    const float* __restrict__ bias,
    __half* __restrict__ Hout,
    const float* __restrict__ att1, const float* __restrict__ att2,
    float* __restrict__ a1, float* __restrict__ a2)
{
    extern __shared__ char dsm[];
    uint32_t sb = smem_to_u32(dsm);
    uint32_t abase = (sb + 1023) & ~1023u;
    uint32_t A_OFF[2] = {abase, abase + 16384};
    uint32_t B_OFF[2] = {abase + 32768, abase + 49152};

    const int tid = threadIdx.x;
    const int wid = tid >> 5;
    const int lane = tid & 31;
    const int wm = wid >> 2;        // 0..1 : M quadrant (64 rows)
    const int wn = wid & 3;         // 0..3 : N quadrant (32 cols = 1 head)
    const int row0 = blockIdx.x * 128;
    const int col0 = blockIdx.y * 128;

    float acc[4][4][4];
#pragma unroll
    for (int a = 0; a < 4; a++)
#pragma unroll
        for (int b = 0; b < 4; b++)
#pragma unroll
            for (int c = 0; c < 4; c++) acc[a][b][c] = 0.f;

    // chunk cc in [0,12): piece = cc>>2 (0:hi*hi 1:hi*lo 2:lo*hi), kc = cc&3
    auto load_chunk = [&](int cc, int buf) {
        int piece = cc >> 2, kc = cc & 3;
        const char* Asrc = (const char*)((piece < 2) ? xhi : xlo);
        const char* Bsrc = (const char*)((piece == 1) ? wlo : whi);
#pragma unroll
        for (int j = 0; j < 4; j++) {   // A: 128 rows x 128B
            int s = tid + j * 256;
            int r = s >> 3, o = s & 7;
            int gr = min(row0 + r, NN - 1);
            uint32_t dst = A_OFF[buf] + SMEM_SWIZZLE_128B(r * 128 + o * 16);
            cp16g(dst, Asrc + (size_t)gr * 512 + kc * 128 + o * 16);
        }
#pragma unroll
        for (int j = 0; j < 4; j++) {   // B: 128 n-rows x 128B
            int s = tid + j * 256;
            int r = s >> 3, o = s & 7;
            uint32_t dst = B_OFF[buf] + SMEM_SWIZZLE_128B(r * 128 + o * 16);
            cp16g(dst, Bsrc + (size_t)(col0 + r) * 512 + kc * 128 + o * 16);
        }
    };

    // ldmatrix lane-address components
    const int a_r = wm * 64 + (lane & 15);                          // + mt*16
    const int a_blk = lane >> 4;                                     // + ks*2
    const int b_r = wn * 32 + ((lane >> 4) & 1) * 8 + (lane & 7);    // + nt2*16
    const int b_blk = (lane >> 3) & 1;                               // + ks*2

    load_chunk(0, 0);
    CP_COMMIT();
    for (int cc = 0; cc < 12; cc++) {
        if (cc + 1 < 12) {
            load_chunk(cc + 1, (cc + 1) & 1);
            CP_COMMIT();
            CP_WAIT1();
        } else {
            CP_WAIT0();
        }
        __syncthreads();
        uint32_t Ab = A_OFF[cc & 1], Bb = B_OFF[cc & 1];
#pragma unroll
        for (int ks = 0; ks < 4; ks++) {
            uint32_t afr[4][4];
#pragma unroll
            for (int mt = 0; mt < 4; mt++) {
                int byte = (a_r + mt * 16) * 128 + (ks * 2 + a_blk) * 16;
                ldsm4(afr[mt], Ab + SMEM_SWIZZLE_128B(byte));
            }
            uint32_t bfr[2][4];
#pragma unroll
            for (int nt2 = 0; nt2 < 2; nt2++) {
                int byte = (b_r + nt2 * 16) * 128 + (ks * 2 + b_blk) * 16;
                ldsm4(bfr[nt2], Bb + SMEM_SWIZZLE_128B(byte));
            }
#pragma unroll
            for (int mt = 0; mt < 4; mt++)
#pragma unroll
                for (int nt = 0; nt < 4; nt++)
                    mma_bf16(acc[mt][nt], afr[mt],
                             bfr[nt >> 1][(nt & 1) * 2], bfr[nt >> 1][(nt & 1) * 2 + 1]);
        }
        __syncthreads();
    }

    // ---- epilogue: bias add, fp16 store, fused per-head attention dots ----
    const int head = blockIdx.y * 4 + wn;
    const int q = lane & 3;
#pragma unroll
    for (int mt = 0; mt < 4; mt++) {
        int r0g = row0 + wm * 64 + mt * 16 + (lane >> 2);
        int r1g = r0g + 8;
        float p1a = 0.f, p1b = 0.f, p2a = 0.f, p2b = 0.f;
#pragma unroll
        for (int nt = 0; nt < 4; nt++) {
            int col = col0 + wn * 32 + nt * 8 + q * 2;
            float bs0 = __ldg(&bias[col]), bs1 = __ldg(&bias[col + 1]);
            float v0 = acc[mt][nt][0] + bs0, v1 = acc[mt][nt][1] + bs1;
            float v2 = acc[mt][nt][2] + bs0, v3 = acc[mt][nt][3] + bs1;
            if (r0g < NN)
                *(__half2*)&Hout[(size_t)r0g * 256 + col] = __floats2half2_rn(v0, v1);
            if (r1g < NN)
                *(__half2*)&Hout[(size_t)r1g * 256 + col] = __floats2half2_rn(v2, v3);
            float t10 = __ldg(&att1[col]), t11 = __ldg(&att1[col + 1]);
            float t20 = __ldg(&att2[col]), t21 = __ldg(&att2[col + 1]);
            p1a += v0 * t10 + v1 * t11;  p1b += v2 * t10 + v3 * t11;
            p2a += v0 * t20 + v1 * t21;  p2b += v2 * t20 + v3 * t21;
        }
#pragma unroll
        for (int o = 1; o <= 2; o <<= 1) {
            p1a += __shfl_xor_sync(0xFFFFFFFFu, p1a, o);
            p1b += __shfl_xor_sync(0xFFFFFFFFu, p1b, o);
            p2a += __shfl_xor_sync(0xFFFFFFFFu, p2a, o);
            p2b += __shfl_xor_sync(0xFFFFFFFFu, p2b, o);
        }
        if (q == 0) {
            if (r0g < NN) { a1[r0g * 8 + head] = p1a; a2[r0g * 8 + head] = p2a; }
            if (r1g < NN) { a1[r1g * 8 + head] = p1b; a2[r1g * 8 + head] = p2b; }
        }
    }
}

// Pass 1: per-(edge,head) leaky-relu logit; atomicMax of monotonic key per (dst,head).
__global__ void edge_logits_kernel(
    const int* __restrict__ src_idx, const int* __restrict__ dst_idx,
    const float* __restrict__ a_s, const float* __restrict__ a_d,
    float* __restrict__ alpha, unsigned* __restrict__ mkey)
{
    int t = blockIdx.x * blockDim.x + threadIdx.x;
    if (t >= EE * HH) return;
    int e = t >> 3, h = t & 7;
    int s = src_idx[e], d = dst_idx[e];
    float v = a_s[s * 8 + h] + a_d[d * 8 + h];
    v = v > 0.f ? v : 0.2f * v;
    alpha[t] = v;
    unsigned u = __float_as_uint(v);
    unsigned key = (u & 0x80000000u) ? ~u : (u | 0x80000000u);
    atomicMax(&mkey[d * 8 + h], key);
}

// Pass 2: e = exp(alpha - max); accumulate denominators.
__global__ void edge_exp_kernel(
    const int* __restrict__ dst_idx,
    float* __restrict__ alpha,
    const unsigned* __restrict__ mkey,
    float* __restrict__ ssum)
{
    int t = blockIdx.x * blockDim.x + threadIdx.x;
    if (t >= EE * HH) return;
    int e = t >> 3, h = t & 7;
    int d = dst_idx[e];
    unsigned key = mkey[d * 8 + h];
    float m = (key & 0x80000000u) ? __uint_as_float(key ^ 0x80000000u)
                                  : __uint_as_float(~key);
    float ev = __expf(alpha[t] - m);
    alpha[t] = ev;
    atomicAdd(&ssum[d * 8 + h], ev);
}

// Pass 3: out[dst] += h_src[src] * alpha/(sum+1e-16). 64 threads per edge,
// fp16 gather (8B/lane), float4 atomic scatter (16B/lane).
__global__ void edge_agg_kernel(
    const int* __restrict__ src_idx, const int* __restrict__ dst_idx,
    const float* __restrict__ ev, const float* __restrict__ ssum,
    const __half* __restrict__ hsrc, float* __restrict__ out)
{
    __shared__ float w[4][8];
    int sub = threadIdx.x >> 6;
    int lane = threadIdx.x & 63;
    int e = blockIdx.x * 4 + sub;
    int s = 0, d = 0;
    if (e < EE) {
        s = src_idx[e]; d = dst_idx[e];
        if (lane < 8) w[sub][lane] = ev[e * 8 + lane] / (ssum[d * 8 + lane] + 1e-16f);
    }
    __syncthreads();
    if (e >= EE) return;
    float wv = w[sub][lane >> 3];
    uint2 raw = *(const uint2*)&hsrc[(size_t)s * 256 + lane * 4];
    __half2 h01 = *reinterpret_cast<__half2*>(&raw.x);
    __half2 h23 = *reinterpret_cast<__half2*>(&raw.y);
    float2 f01 = __half22float2(h01);
    float2 f23 = __half22float2(h23);
    float4 r = make_float4(f01.x * wv, f01.y * wv, f23.x * wv, f23.y * wv);
    atomicAdd((float4*)&out[(size_t)d * 256 + lane * 4], r);
}

// BN stats: per-column sum / sumsq of relu(out) over row chunks.
__global__ void bn_stats_kernel(const float* __restrict__ out, float* __restrict__ stat,
                                int rows_per_block)
{
    int c = threadIdx.x;
    int r0 = blockIdx.x * rows_per_block;
    int r1 = min(r0 + rows_per_block, NN);
    float s = 0.f, q = 0.f;
    for (int r = r0; r < r1; r++) {
        float v = fmaxf(out[(size_t)r * 256 + c], 0.f);
        s += v; q += v * v;
    }
    atomicAdd(&stat[c], s);
    atomicAdd(&stat[256 + c], q);
}

__global__ void bn_finalize_kernel(const float* __restrict__ stat,
                                   const float* __restrict__ gamma,
                                   const float* __restrict__ beta,
                                   float* __restrict__ scale, float* __restrict__ shift)
{
    int c = threadIdx.x;
    const float inv = 1.f / (float)NN;
    float mu = stat[c] * inv;
    float var = stat[256 + c] * inv - mu * mu;
    float sc = gamma[c] * rsqrtf(var + 1e-5f);
    scale[c] = sc;
    shift[c] = beta[c] - mu * sc;
}

// Final: per label edge dot of normalized features, sigmoid. One warp per edge.
__global__ void edge_predict_kernel(
    const int* __restrict__ li, const int* __restrict__ lj,
    const float* __restrict__ outr, const float* __restrict__ outc,
    const float* __restrict__ scale_r, const float* __restrict__ shift_r,
    const float* __restrict__ scale_c, const float* __restrict__ shift_c,
    float* __restrict__ y)
{
    int warp = (blockIdx.x * blockDim.x + threadIdx.x) >> 5;
    int lane = threadIdx.x & 31;
    if (warp >= EL) return;
    int i = li[warp], j = lj[warp];
    float acc = 0.f;
#pragma unroll
    for (int jj = 0; jj < 8; jj++) {
        int c = lane + 32 * jj;
        float zr = fmaxf(outr[(size_t)i * 256 + c], 0.f) * scale_r[c] + shift_r[c];
        float zc = fmaxf(outc[(size_t)j * 256 + c], 0.f) * scale_c[c] + shift_c[c];
        acc += zr * zc;
    }
#pragma unroll
    for (int o = 16; o; o >>= 1) acc += __shfl_down_sync(0xFFFFFFFFu, acc, o);
    if (lane == 0) y[warp] = 1.f / (1.f + __expf(-acc));
}

// ---------------- host launch ----------------

extern "C" void kernel_launch(void* const* d_in, const int* in_sizes, int n_in,
                              void* d_out, int out_size)
{
    const float* x_req   = (const float*)d_in[0];
    const float* x_code  = (const float*)d_in[1];
    const int*   ei_rc   = (const int*)d_in[2];
    const int*   ei_cr   = (const int*)d_in[3];
    const int*   eli     = (const int*)d_in[4];
    const float* W_req   = (const float*)d_in[5];
    const float* b_req   = (const float*)d_in[6];
    const float* W_code  = (const float*)d_in[7];
    const float* b_code  = (const float*)d_in[8];
    const float* att_src_rc = (const float*)d_in[9];
    const float* att_dst_rc = (const float*)d_in[10];
    const float* att_src_cr = (const float*)d_in[11];
    const float* att_dst_cr = (const float*)d_in[12];
    // d_in[13..15]: k_W, k_b, q -> identity here (softmax over single metapath)
    const float* gamma = (const float*)d_in[16];
    const float* beta  = (const float*)d_in[17];
    float* y = (float*)d_out;

    float *out_base, *a_base, *ssum_base, *alpha_base, *bn_base, *scale_base, *shift_base;
    unsigned* mkey_base;
    __half* h_base;
    __nv_bfloat16 *xhi_base, *xlo_base, *whi_base, *wlo_base;
    cudaGetSymbolAddress((void**)&h_base, g_h);
    cudaGetSymbolAddress((void**)&out_base, g_out);
    cudaGetSymbolAddress((void**)&a_base, g_a);
    cudaGetSymbolAddress((void**)&mkey_base, g_mkey);
    cudaGetSymbolAddress((void**)&ssum_base, g_ssum);
    cudaGetSymbolAddress((void**)&alpha_base, g_alpha);
    cudaGetSymbolAddress((void**)&bn_base, g_bnstat);
    cudaGetSymbolAddress((void**)&scale_base, g_scale);
    cudaGetSymbolAddress((void**)&shift_base, g_shift);
    cudaGetSymbolAddress((void**)&xhi_base, g_xhi);
    cudaGetSymbolAddress((void**)&xlo_base, g_xlo);
    cudaGetSymbolAddress((void**)&whi_base, g_whi);
    cudaGetSymbolAddress((void**)&wlo_base, g_wlo);

    __half* h_req  = h_base;
    __half* h_code = h_base + (size_t)NN * CC;
    float* out_req  = out_base;
    float* out_code = out_base + (size_t)NN * CC;
    float* a_src_rc = a_base + 0 * (size_t)NN * HH;
    float* a_dst_rc = a_base + 1 * (size_t)NN * HH;
    float* a_src_cr = a_base + 2 * (size_t)NN * HH;
    float* a_dst_cr = a_base + 3 * (size_t)NN * HH;
    unsigned* mkey_code = mkey_base;
    unsigned* mkey_req  = mkey_base + (size_t)NN * HH;
    float* ssum_code = ssum_base;
    float* ssum_req  = ssum_base + (size_t)NN * HH;
    float* alpha_rc = alpha_base;
    float* alpha_cr = alpha_base + (size_t)EE * HH;
    float* bn_req  = bn_base;
    float* bn_code = bn_base + 2 * CC;
    float* scale_req  = scale_base;
    float* scale_code = scale_base + CC;
    float* shift_req  = shift_base;
    float* shift_code = shift_base + CC;

    const int* src_rc = ei_rc;          const int* dst_rc = ei_rc + EE;
    const int* src_cr = ei_cr;          const int* dst_cr = ei_cr + EE;
    const int* li = eli;                const int* lj = eli + EL;

    // ---- zero scratch ----
    zero_kernel<<<2048, 256>>>((float4*)out_base, (2 * NN * CC) / 4);
    zero_kernel<<<512, 256>>>((float4*)mkey_base, (2 * NN * HH) / 4);
    zero_kernel<<<512, 256>>>((float4*)ssum_base, (2 * NN * HH) / 4);
    zero_kernel<<<1, 256>>>((float4*)bn_base, (2 * 2 * CC) / 4);

    // ---- bf16 hi/lo splits ----
    {
        int n4x = NN * CC / 4;
        int gx = (n4x + 255) / 256;
        split_kernel<<<gx, 256>>>((const float4*)x_req,
            (uint2*)(xhi_base), (uint2*)(xlo_base), n4x);
        split_kernel<<<gx, 256>>>((const float4*)x_code,
            (uint2*)(xhi_base + (size_t)NN * CC), (uint2*)(xlo_base + (size_t)NN * CC), n4x);
        int n4w = CC * CC / 4;
        int gw = (n4w + 255) / 256;
        split_kernel<<<gw, 256>>>((const float4*)W_req,
            (uint2*)(whi_base), (uint2*)(wlo_base), n4w);
        split_kernel<<<gw, 256>>>((const float4*)W_code,
            (uint2*)(whi_base + (size_t)CC * CC), (uint2*)(wlo_base + (size_t)CC * CC), n4w);
    }

    // ---- HMMA GEMM with fused bias + attention dots + fp16 h store ----
    const int SMEM_GEMM = 1024 + 4 * 16384;  // 66.5 KB
    cudaFuncSetAttribute(mma_gemm_kernel, cudaFuncAttributeMaxDynamicSharedMemorySize, SMEM_GEMM);
    dim3 gg((NN + 127) / 128, 2);
    mma_gemm_kernel<<<gg, 256, SMEM_GEMM>>>(
        xhi_base, xlo_base, whi_base, wlo_base, b_req, h_req,
        att_src_rc, att_dst_cr, a_src_rc, a_dst_cr);
    mma_gemm_kernel<<<gg, 256, SMEM_GEMM>>>(
        xhi_base + (size_t)NN * CC, xlo_base + (size_t)NN * CC,
        whi_base + (size_t)CC * CC, wlo_base + (size_t)CC * CC, b_code, h_code,
        att_dst_rc, att_src_cr, a_dst_rc, a_src_cr);

    // ---- edge softmax pass 1: logits + segment max ----
    int eblk = (EE * HH + 255) / 256;
    edge_logits_kernel<<<eblk, 256>>>(src_rc, dst_rc, a_src_rc, a_dst_rc, alpha_rc, mkey_code);
    edge_logits_kernel<<<eblk, 256>>>(src_cr, dst_cr, a_src_cr, a_dst_cr, alpha_cr, mkey_req);

    // ---- pass 2: exp + segment sum ----
    edge_exp_kernel<<<eblk, 256>>>(dst_rc, alpha_rc, mkey_code, ssum_code);
    edge_exp_kernel<<<eblk, 256>>>(dst_cr, alpha_cr, mkey_req, ssum_req);

    // ---- pass 3: weighted aggregation ----
    edge_agg_kernel<<<EE / 4, 256>>>(src_rc, dst_rc, alpha_rc, ssum_code, h_req, out_code);
    edge_agg_kernel<<<EE / 4, 256>>>(src_cr, dst_cr, alpha_cr, ssum_req, h_code, out_req);

    // ---- batchnorm (relu fused at read) ----
    int rpb = (NN + 511) / 512;
    bn_stats_kernel<<<512, 256>>>(out_req, bn_req, rpb);
    bn_stats_kernel<<<512, 256>>>(out_code, bn_code, rpb);
    bn_finalize_kernel<<<1, 256>>>(bn_req, gamma, beta, scale_req, shift_req);
    bn_finalize_kernel<<<1, 256>>>(bn_code, gamma, beta, scale_code, shift_code);

    // ---- edge classifier ----
    edge_predict_kernel<<<(EL * 32 + 255) / 256, 256>>>(
        li, lj, out_req, out_code, scale_req, shift_req, scale_code, shift_code, y);
}

// round 16
// speedup vs baseline: 1.9224x; 1.3059x over previous
#include <cuda_runtime.h>
#include <cuda_bf16.h>
#include <cuda_fp16.h>
#include <cstdint>

// Problem constants
constexpr int NN = 100000;   // N_REQ == N_CODE
constexpr int CC = 256;      // C_OUT == C_IN
constexpr int HH = 8;        // heads
constexpr int EE = 500000;   // edges per type
constexpr int EL = 200000;   // label edges
constexpr int SCAN_BS = 1024;
constexpr int SCAN_NB = (NN + SCAN_BS - 1) / SCAN_BS;   // 98

// ---------------- device scratch (static, no allocations) ----------------
__device__ __align__(16) __half    g_h[2][NN * CC];       // projected features (fp16)
__device__ __align__(16) float     g_out[2][NN * CC];     // aggregated (relu'd)
__device__ __align__(16) float     g_a[4][NN * HH];       // attention scalars
__device__ __align__(16) float     g_bnstat[2][2 * CC];
__device__ __align__(16) float     g_scale[2][CC];
__device__ __align__(16) float     g_shift[2][CC];
// CSR build scratch
__device__ __align__(16) int       g_cnt[2][NN];
__device__ __align__(16) int       g_wptr[2][NN];
__device__ __align__(16) int       g_off[2][NN];
__device__ __align__(16) int       g_bsum[2][128];
__device__ __align__(16) int       g_auxex[2][128];
__device__ __align__(16) int       g_csr_src[2][EE];
// bf16 hi/lo split buffers for tensor-core GEMM
__device__ __align__(16) __nv_bfloat16 g_xhi[2][NN * CC];
__device__ __align__(16) __nv_bfloat16 g_xlo[2][NN * CC];
__device__ __align__(16) __nv_bfloat16 g_whi[2][CC * CC];
__device__ __align__(16) __nv_bfloat16 g_wlo[2][CC * CC];

// ---------------- PTX helpers (plain sm_80+ features only) ----------------
__device__ __forceinline__ uint32_t smem_to_u32(const void* p) {
    uint32_t a;
    asm("{ .reg .u64 t; cvta.to.shared.u64 t, %1; cvt.u32.u64 %0, t; }" : "=r"(a) : "l"(p));
    return a;
}
#define SMEM_SWIZZLE_128B(o) ((o) ^ (((o) >> 3) & 0x70))

__device__ __forceinline__ void cp16g(uint32_t dst, const void* src) {
    asm volatile("cp.async.cg.shared.global [%0], [%1], 16;" :: "r"(dst), "l"(src));
}
#define CP_COMMIT() asm volatile("cp.async.commit_group;" ::: "memory")
#define CP_WAIT1()  asm volatile("cp.async.wait_group 1;" ::: "memory")
#define CP_WAIT0()  asm volatile("cp.async.wait_group 0;" ::: "memory")

__device__ __forceinline__ void ldsm4(uint32_t* r, uint32_t addr) {
    asm volatile("ldmatrix.sync.aligned.m8n8.x4.shared.b16 {%0,%1,%2,%3}, [%4];"
        : "=r"(r[0]), "=r"(r[1]), "=r"(r[2]), "=r"(r[3]) : "r"(addr));
}

__device__ __forceinline__ void mma_bf16(float* c, const uint32_t* a, uint32_t b0, uint32_t b1) {
    asm volatile("mma.sync.aligned.m16n8k16.row.col.f32.bf16.bf16.f32 "
        "{%0,%1,%2,%3}, {%4,%5,%6,%7}, {%8,%9}, {%0,%1,%2,%3};"
        : "+f"(c[0]), "+f"(c[1]), "+f"(c[2]), "+f"(c[3])
        : "r"(a[0]), "r"(a[1]), "r"(a[2]), "r"(a[3]), "r"(b0), "r"(b1));
}

// ---------------- generic small kernels ----------------

__global__ void zero_kernel(float4* p, int n4) {
    int i = blockIdx.x * blockDim.x + threadIdx.x;
    int stride = gridDim.x * blockDim.x;
    float4 z = make_float4(0.f, 0.f, 0.f, 0.f);
    for (; i < n4; i += stride) p[i] = z;
}

// split fp32 -> bf16 hi + bf16 lo (exact residual split)
__global__ void split_kernel(const float4* __restrict__ x,
                             uint2* __restrict__ hi, uint2* __restrict__ lo, int n4) {
    int i = blockIdx.x * blockDim.x + threadIdx.x;
    if (i >= n4) return;
    float4 v = x[i];
    __nv_bfloat16 h0 = __float2bfloat16(v.x), h1 = __float2bfloat16(v.y);
    __nv_bfloat16 h2 = __float2bfloat16(v.z), h3 = __float2bfloat16(v.w);
    __nv_bfloat16 l0 = __float2bfloat16(v.x - __bfloat162float(h0));
    __nv_bfloat16 l1 = __float2bfloat16(v.y - __bfloat162float(h1));
    __nv_bfloat16 l2 = __float2bfloat16(v.z - __bfloat162float(h2));
    __nv_bfloat16 l3 = __float2bfloat16(v.w - __bfloat162float(h3));
    uint2 H, L;
    H.x = ((uint32_t)__bfloat16_as_ushort(h1) << 16) | __bfloat16_as_ushort(h0);
    H.y = ((uint32_t)__bfloat16_as_ushort(h3) << 16) | __bfloat16_as_ushort(h2);
    L.x = ((uint32_t)__bfloat16_as_ushort(l1) << 16) | __bfloat16_as_ushort(l0);
    L.y = ((uint32_t)__bfloat16_as_ushort(l3) << 16) | __bfloat16_as_ushort(l2);
    hi[i] = H;
    lo[i] = L;
}

// ---------------- CSR build (histogram + scan + fill) ----------------

__global__ void count_kernel(const int* __restrict__ dst, int* __restrict__ cnt) {
    int e = blockIdx.x * blockDim.x + threadIdx.x;
    if (e < EE) atomicAdd(&cnt[dst[e]], 1);
}

__global__ void blocksum_kernel(const int* __restrict__ cnt, int* __restrict__ bsum) {
    __shared__ int s[SCAN_BS];
    int i = blockIdx.x * SCAN_BS + threadIdx.x;
    s[threadIdx.x] = (i < NN) ? cnt[i] : 0;
    __syncthreads();
    for (int o = SCAN_BS / 2; o; o >>= 1) {
        if (threadIdx.x < o) s[threadIdx.x] += s[threadIdx.x + o];
        __syncthreads();
    }
    if (threadIdx.x == 0) bsum[blockIdx.x] = s[0];
}

__global__ void auxscan_kernel(const int* __restrict__ bsum, int* __restrict__ auxex) {
    __shared__ int s[128];
    int t = threadIdx.x;
    int v0 = (t < SCAN_NB) ? bsum[t] : 0;
    s[t] = v0;
    __syncthreads();
    for (int o = 1; o < 128; o <<= 1) {
        int v = (t >= o) ? s[t - o] : 0;
        __syncthreads();
        s[t] += v;
        __syncthreads();
    }
    if (t < SCAN_NB) auxex[t] = s[t] - v0;   // exclusive
}

__global__ void offsets_kernel(const int* __restrict__ cnt, const int* __restrict__ auxex,
                               int* __restrict__ off) {
    __shared__ int s[SCAN_BS];
    int i = blockIdx.x * SCAN_BS + threadIdx.x;
    int v0 = (i < NN) ? cnt[i] : 0;
    s[threadIdx.x] = v0;
    __syncthreads();
    for (int o = 1; o < SCAN_BS; o <<= 1) {
        int v = (threadIdx.x >= o) ? s[threadIdx.x - o] : 0;
        __syncthreads();
        s[threadIdx.x] += v;
        __syncthreads();
    }
    if (i < NN) off[i] = auxex[blockIdx.x] + s[threadIdx.x] - v0;  // exclusive
}

__global__ void fill_kernel(const int* __restrict__ src, const int* __restrict__ dst,
                            const int* __restrict__ off, int* __restrict__ wptr,
                            int* __restrict__ csr_src) {
    int e = blockIdx.x * blockDim.x + threadIdx.x;
    if (e >= EE) return;
    int d = dst[e];
    int pos = off[d] + atomicAdd(&wptr[d], 1);
    csr_src[pos] = src[e];
}

// ---------------- HMMA GEMM (bf16 hi/lo 3-term) ----------------
// H[M,N=256] = Xhi*Whi^T + Xhi*Wlo^T + Xlo*Whi^T + bias.
// CTA: 128(M) x 128(N) (blockIdx.y = N half), 8 warps of 64x32.
// Fused epilogue: fp16 h store + per-head attention dots.
__global__ void __launch_bounds__(256, 2) mma_gemm_kernel(
    const __nv_bfloat16* __restrict__ xhi, const __nv_bfloat16* __restrict__ xlo,
    const __nv_bfloat16* __restrict__ whi, const __nv_bfloat16* __restrict__ wlo,
    const float* __restrict__ bias,
    __half* __restrict__ Hout,
    const float* __restrict__ att1, const float* __restrict__ att2,
    float* __restrict__ a1, float* __restrict__ a2)
{
    extern __shared__ char dsm[];
    uint32_t sb = smem_to_u32(dsm);
    uint32_t abase = (sb + 1023) & ~1023u;
    uint32_t A_OFF[2] = {abase, abase + 16384};
    uint32_t B_OFF[2] = {abase + 32768, abase + 49152};

    const int tid = threadIdx.x;
    const int wid = tid >> 5;
    const int lane = tid & 31;
    const int wm = wid >> 2;
    const int wn = wid & 3;
    const int row0 = blockIdx.x * 128;
    const int col0 = blockIdx.y * 128;

    float acc[4][4][4];
#pragma unroll
    for (int a = 0; a < 4; a++)
#pragma unroll
        for (int b = 0; b < 4; b++)
#pragma unroll
            for (int c = 0; c < 4; c++) acc[a][b][c] = 0.f;

    auto load_chunk = [&](int cc, int buf) {
        int piece = cc >> 2, kc = cc & 3;
        const char* Asrc = (const char*)((piece < 2) ? xhi : xlo);
        const char* Bsrc = (const char*)((piece == 1) ? wlo : whi);
#pragma unroll
        for (int j = 0; j < 4; j++) {
            int s = tid + j * 256;
            int r = s >> 3, o = s & 7;
            int gr = min(row0 + r, NN - 1);
            uint32_t dst = A_OFF[buf] + SMEM_SWIZZLE_128B(r * 128 + o * 16);
            cp16g(dst, Asrc + (size_t)gr * 512 + kc * 128 + o * 16);
        }
#pragma unroll
        for (int j = 0; j < 4; j++) {
            int s = tid + j * 256;
            int r = s >> 3, o = s & 7;
            uint32_t dst = B_OFF[buf] + SMEM_SWIZZLE_128B(r * 128 + o * 16);
            cp16g(dst, Bsrc + (size_t)(col0 + r) * 512 + kc * 128 + o * 16);
        }
    };

    const int a_r = wm * 64 + (lane & 15);
    const int a_blk = lane >> 4;
    const int b_r = wn * 32 + ((lane >> 4) & 1) * 8 + (lane & 7);
    const int b_blk = (lane >> 3) & 1;

    load_chunk(0, 0);
    CP_COMMIT();
    for (int cc = 0; cc < 12; cc++) {
        if (cc + 1 < 12) {
            load_chunk(cc + 1, (cc + 1) & 1);
            CP_COMMIT();
            CP_WAIT1();
        } else {
            CP_WAIT0();
        }
        __syncthreads();
        uint32_t Ab = A_OFF[cc & 1], Bb = B_OFF[cc & 1];
#pragma unroll
        for (int ks = 0; ks < 4; ks++) {
            uint32_t afr[4][4];
#pragma unroll
            for (int mt = 0; mt < 4; mt++) {
                int byte = (a_r + mt * 16) * 128 + (ks * 2 + a_blk) * 16;
                ldsm4(afr[mt], Ab + SMEM_SWIZZLE_128B(byte));
            }
            uint32_t bfr[2][4];
#pragma unroll
            for (int nt2 = 0; nt2 < 2; nt2++) {
                int byte = (b_r + nt2 * 16) * 128 + (ks * 2 + b_blk) * 16;
                ldsm4(bfr[nt2], Bb + SMEM_SWIZZLE_128B(byte));
            }
#pragma unroll
            for (int mt = 0; mt < 4; mt++)
#pragma unroll
                for (int nt = 0; nt < 4; nt++)
                    mma_bf16(acc[mt][nt], afr[mt],
                             bfr[nt >> 1][(nt & 1) * 2], bfr[nt >> 1][(nt & 1) * 2 + 1]);
        }
        __syncthreads();
    }

    const int head = blockIdx.y * 4 + wn;
    const int q = lane & 3;
#pragma unroll
    for (int mt = 0; mt < 4; mt++) {
        int r0g = row0 + wm * 64 + mt * 16 + (lane >> 2);
        int r1g = r0g + 8;
        float p1a = 0.f, p1b = 0.f, p2a = 0.f, p2b = 0.f;
#pragma unroll
        for (int nt = 0; nt < 4; nt++) {
            int col = col0 + wn * 32 + nt * 8 + q * 2;
            float bs0 = __ldg(&bias[col]), bs1 = __ldg(&bias[col + 1]);
            float v0 = acc[mt][nt][0] + bs0, v1 = acc[mt][nt][1] + bs1;
            float v2 = acc[mt][nt][2] + bs0, v3 = acc[mt][nt][3] + bs1;
            if (r0g < NN)
                *(__half2*)&Hout[(size_t)r0g * 256 + col] = __floats2half2_rn(v0, v1);
            if (r1g < NN)
                *(__half2*)&Hout[(size_t)r1g * 256 + col] = __floats2half2_rn(v2, v3);
            float t10 = __ldg(&att1[col]), t11 = __ldg(&att1[col + 1]);
            float t20 = __ldg(&att2[col]), t21 = __ldg(&att2[col + 1]);
            p1a += v0 * t10 + v1 * t11;  p1b += v2 * t10 + v3 * t11;
            p2a += v0 * t20 + v1 * t21;  p2b += v2 * t20 + v3 * t21;
        }
#pragma unroll
        for (int o = 1; o <= 2; o <<= 1) {
            p1a += __shfl_xor_sync(0xFFFFFFFFu, p1a, o);
            p1b += __shfl_xor_sync(0xFFFFFFFFu, p1b, o);
            p2a += __shfl_xor_sync(0xFFFFFFFFu, p2a, o);
            p2b += __shfl_xor_sync(0xFFFFFFFFu, p2b, o);
        }
        if (q == 0) {
            if (r0g < NN) { a1[r0g * 8 + head] = p1a; a2[r0g * 8 + head] = p2a; }
            if (r1g < NN) { a1[r1g * 8 + head] = p1b; a2[r1g * 8 + head] = p2b; }
        }
    }
}

// ---------------- fused softmax + aggregation + relu + BN partials ----------------
// One warp per dst node (persistent grid-stride). No atomics on the feature matrix.
// pass A: per-head max over edge list (gather of a_s)
// pass B: w = exp(logit - max); acc += w * h_src  (unnormalized; divide at end)
// epilogue: relu, fp32 out write, per-warp smem BN partials -> global atomics once/CTA.
__global__ void __launch_bounds__(256) agg_kernel(
    const int* __restrict__ off, const int* __restrict__ csr_src,
    const float* __restrict__ a_s, const float* __restrict__ a_d,
    const __half* __restrict__ hsrc, float* __restrict__ out,
    float* __restrict__ stat)
{
    __shared__ float sm[8][512];   // per-warp [sum(256), sumsq(256)]
    const int tid = threadIdx.x;
    const int wid = tid >> 5;
    const int lane = tid & 31;
    const int h = lane & 7;
    const int myhead = lane >> 2;          // head of this lane's 8 columns

    // zero per-warp BN accumulators
#pragma unroll
    for (int j = 0; j < 16; j++) sm[wid][lane + j * 32] = 0.f;
    __syncwarp();

    const int nwarps = gridDim.x * 8;
    for (int d = blockIdx.x * 8 + wid; d < NN; d += nwarps) {
        int beg = off[d];
        int end = (d == NN - 1) ? EE : off[d + 1];
        float ad = a_d[d * 8 + h];

        // pass A: per-head max (4 edges in parallel: sub = lane>>3)
        float mx = -1e30f;
        for (int i = beg + (lane >> 3); i < end; i += 4) {
            int s = csr_src[i];
            float v = a_s[s * 8 + h] + ad;
            v = v > 0.f ? v : 0.2f * v;
            mx = fmaxf(mx, v);
        }
        mx = fmaxf(mx, __shfl_xor_sync(0xFFFFFFFFu, mx, 8));
        mx = fmaxf(mx, __shfl_xor_sync(0xFFFFFFFFu, mx, 16));

        // pass B: accumulate unnormalized weighted sum
        float acc[8];
#pragma unroll
        for (int j = 0; j < 8; j++) acc[j] = 0.f;
        float wsum = 0.f;
        for (int i = beg; i < end; i++) {
            int s = csr_src[i];
            float v = a_s[s * 8 + h] + ad;
            v = v > 0.f ? v : 0.2f * v;
            float w = __expf(v - mx);
            wsum += w;
            float wh = __shfl_sync(0xFFFFFFFFu, w, myhead);
            uint4 raw = *(const uint4*)&hsrc[(size_t)s * 256 + lane * 8];
            __half2 p0 = *reinterpret_cast<__half2*>(&raw.x);
            __half2 p1 = *reinterpret_cast<__half2*>(&raw.y);
            __half2 p2 = *reinterpret_cast<__half2*>(&raw.z);
            __half2 p3 = *reinterpret_cast<__half2*>(&raw.w);
            float2 f0 = __half22float2(p0), f1 = __half22float2(p1);
            float2 f2 = __half22float2(p2), f3 = __half22float2(p3);
            acc[0] += f0.x * wh; acc[1] += f0.y * wh;
            acc[2] += f1.x * wh; acc[3] += f1.y * wh;
            acc[4] += f2.x * wh; acc[5] += f2.y * wh;
            acc[6] += f3.x * wh; acc[7] += f3.y * wh;
        }
        float ws = __shfl_sync(0xFFFFFFFFu, wsum, myhead);
        float inv = 1.f / (ws + 1e-16f);

        // relu + write + BN partials
        float ovals[8];
#pragma unroll
        for (int j = 0; j < 8; j++) {
            float val = fmaxf(acc[j] * inv, 0.f);
            ovals[j] = val;
            int c = lane * 8 + j;
            sm[wid][c] += val;
            sm[wid][256 + c] += val * val;
        }
        *(float4*)&out[(size_t)d * 256 + lane * 8] =
            make_float4(ovals[0], ovals[1], ovals[2], ovals[3]);
        *(float4*)&out[(size_t)d * 256 + lane * 8 + 4] =
            make_float4(ovals[4], ovals[5], ovals[6], ovals[7]);
    }

    __syncthreads();
    // reduce 8 warp regions -> global stat (512 atomics per CTA)
    for (int t = tid; t < 512; t += 256) {
        float s = 0.f;
#pragma unroll
        for (int w = 0; w < 8; w++) s += sm[w][t];
        atomicAdd(&stat[t], s);
    }
}

__global__ void bn_finalize_kernel(const float* __restrict__ stat,
                                   const float* __restrict__ gamma,
                                   const float* __restrict__ beta,
                                   float* __restrict__ scale, float* __restrict__ shift)
{
    int c = threadIdx.x;
    const float inv = 1.f / (float)NN;
    float mu = stat[c] * inv;
    float var = stat[256 + c] * inv - mu * mu;
    float sc = gamma[c] * rsqrtf(var + 1e-5f);
    scale[c] = sc;
    shift[c] = beta[c] - mu * sc;
}

// Final: per label edge dot of normalized features, sigmoid. One warp per edge.
// (out already relu'd)
__global__ void edge_predict_kernel(
    const int* __restrict__ li, const int* __restrict__ lj,
    const float* __restrict__ outr, const float* __restrict__ outc,
    const float* __restrict__ scale_r, const float* __restrict__ shift_r,
    const float* __restrict__ scale_c, const float* __restrict__ shift_c,
    float* __restrict__ y)
{
    int warp = (blockIdx.x * blockDim.x + threadIdx.x) >> 5;
    int lane = threadIdx.x & 31;
    if (warp >= EL) return;
    int i = li[warp], j = lj[warp];
    float acc = 0.f;
#pragma unroll
    for (int jj = 0; jj < 8; jj++) {
        int c = lane + 32 * jj;
        float zr = outr[(size_t)i * 256 + c] * scale_r[c] + shift_r[c];
        float zc = outc[(size_t)j * 256 + c] * scale_c[c] + shift_c[c];
        acc += zr * zc;
    }
#pragma unroll
    for (int o = 16; o; o >>= 1) acc += __shfl_down_sync(0xFFFFFFFFu, acc, o);
    if (lane == 0) y[warp] = 1.f / (1.f + __expf(-acc));
}

// ---------------- host launch ----------------

extern "C" void kernel_launch(void* const* d_in, const int* in_sizes, int n_in,
                              void* d_out, int out_size)
{
    const float* x_req   = (const float*)d_in[0];
    const float* x_code  = (const float*)d_in[1];
    const int*   ei_rc   = (const int*)d_in[2];
    const int*   ei_cr   = (const int*)d_in[3];
    const int*   eli     = (const int*)d_in[4];
    const float* W_req   = (const float*)d_in[5];
    const float* b_req   = (const float*)d_in[6];
    const float* W_code  = (const float*)d_in[7];
    const float* b_code  = (const float*)d_in[8];
    const float* att_src_rc = (const float*)d_in[9];
    const float* att_dst_rc = (const float*)d_in[10];
    const float* att_src_cr = (const float*)d_in[11];
    const float* att_dst_cr = (const float*)d_in[12];
    // d_in[13..15]: k_W, k_b, q -> identity here (softmax over single metapath)
    const float* gamma = (const float*)d_in[16];
    const float* beta  = (const float*)d_in[17];
    float* y = (float*)d_out;

    float *out_base, *a_base, *bn_base, *scale_base, *shift_base;
    int *cnt_base, *wptr_base, *off_base, *bsum_base, *auxex_base, *csr_base;
    __half* h_base;
    __nv_bfloat16 *xhi_base, *xlo_base, *whi_base, *wlo_base;
    cudaGetSymbolAddress((void**)&h_base, g_h);
    cudaGetSymbolAddress((void**)&out_base, g_out);
    cudaGetSymbolAddress((void**)&a_base, g_a);
    cudaGetSymbolAddress((void**)&bn_base, g_bnstat);
    cudaGetSymbolAddress((void**)&scale_base, g_scale);
    cudaGetSymbolAddress((void**)&shift_base, g_shift);
    cudaGetSymbolAddress((void**)&cnt_base, g_cnt);
    cudaGetSymbolAddress((void**)&wptr_base, g_wptr);
    cudaGetSymbolAddress((void**)&off_base, g_off);
    cudaGetSymbolAddress((void**)&bsum_base, g_bsum);
    cudaGetSymbolAddress((void**)&auxex_base, g_auxex);
    cudaGetSymbolAddress((void**)&csr_base, g_csr_src);
    cudaGetSymbolAddress((void**)&xhi_base, g_xhi);
    cudaGetSymbolAddress((void**)&xlo_base, g_xlo);
    cudaGetSymbolAddress((void**)&whi_base, g_whi);
    cudaGetSymbolAddress((void**)&wlo_base, g_wlo);

    __half* h_req  = h_base;
    __half* h_code = h_base + (size_t)NN * CC;
    float* out_req  = out_base;
    float* out_code = out_base + (size_t)NN * CC;
    float* a_src_rc = a_base + 0 * (size_t)NN * HH;
    float* a_dst_rc = a_base + 1 * (size_t)NN * HH;
    float* a_src_cr = a_base + 2 * (size_t)NN * HH;
    float* a_dst_cr = a_base + 3 * (size_t)NN * HH;
    float* bn_req  = bn_base;
    float* bn_code = bn_base + 2 * CC;
    float* scale_req  = scale_base;
    float* scale_code = scale_base + CC;
    float* shift_req  = shift_base;
    float* shift_code = shift_base + CC;

    const int* src_rc = ei_rc;          const int* dst_rc = ei_rc + EE;
    const int* src_cr = ei_cr;          const int* dst_cr = ei_cr + EE;
    const int* li = eli;                const int* lj = eli + EL;

    int* cnt_rc  = cnt_base;            int* cnt_cr  = cnt_base + NN;
    int* wptr_rc = wptr_base;           int* wptr_cr = wptr_base + NN;
    int* off_rc  = off_base;            int* off_cr  = off_base + NN;
    int* bsum_rc = bsum_base;           int* bsum_cr = bsum_base + 128;
    int* aux_rc  = auxex_base;          int* aux_cr  = auxex_base + 128;
    int* csr_rc  = csr_base;            int* csr_cr  = csr_base + EE;

    // ---- zero small scratch ----
    zero_kernel<<<128, 256>>>((float4*)cnt_base, (2 * NN) / 4);
    zero_kernel<<<128, 256>>>((float4*)wptr_base, (2 * NN) / 4);
    zero_kernel<<<1, 256>>>((float4*)bn_base, (2 * 2 * CC) / 4);

    // ---- CSR build (both edge types) ----
    int eg = (EE + 255) / 256;
    count_kernel<<<eg, 256>>>(dst_rc, cnt_rc);
    count_kernel<<<eg, 256>>>(dst_cr, cnt_cr);
    blocksum_kernel<<<SCAN_NB, SCAN_BS>>>(cnt_rc, bsum_rc);
    blocksum_kernel<<<SCAN_NB, SCAN_BS>>>(cnt_cr, bsum_cr);
    auxscan_kernel<<<1, 128>>>(bsum_rc, aux_rc);
    auxscan_kernel<<<1, 128>>>(bsum_cr, aux_cr);
    offsets_kernel<<<SCAN_NB, SCAN_BS>>>(cnt_rc, aux_rc, off_rc);
    offsets_kernel<<<SCAN_NB, SCAN_BS>>>(cnt_cr, aux_cr, off_cr);
    fill_kernel<<<eg, 256>>>(src_rc, dst_rc, off_rc, wptr_rc, csr_rc);
    fill_kernel<<<eg, 256>>>(src_cr, dst_cr, off_cr, wptr_cr, csr_cr);

    // ---- bf16 hi/lo splits ----
    {
        int n4x = NN * CC / 4;
        int gx = (n4x + 255) / 256;
        split_kernel<<<gx, 256>>>((const float4*)x_req,
            (uint2*)(xhi_base), (uint2*)(xlo_base), n4x);
        split_kernel<<<gx, 256>>>((const float4*)x_code,
            (uint2*)(xhi_base + (size_t)NN * CC), (uint2*)(xlo_base + (size_t)NN * CC), n4x);
        int n4w = CC * CC / 4;
        int gw = (n4w + 255) / 256;
        split_kernel<<<gw, 256>>>((const float4*)W_req,
            (uint2*)(whi_base), (uint2*)(wlo_base), n4w);
        split_kernel<<<gw, 256>>>((const float4*)W_code,
            (uint2*)(whi_base + (size_t)CC * CC), (uint2*)(wlo_base + (size_t)CC * CC), n4w);
    }

    // ---- HMMA GEMM with fused bias + attention dots + fp16 h store ----
    const int SMEM_GEMM = 1024 + 4 * 16384;  // 66.5 KB
    cudaFuncSetAttribute(mma_gemm_kernel, cudaFuncAttributeMaxDynamicSharedMemorySize, SMEM_GEMM);
    dim3 gg((NN + 127) / 128, 2);
    mma_gemm_kernel<<<gg, 256, SMEM_GEMM>>>(
        xhi_base, xlo_base, whi_base, wlo_base, b_req, h_req,
        att_src_rc, att_dst_cr, a_src_rc, a_dst_cr);
    mma_gemm_kernel<<<gg, 256, SMEM_GEMM>>>(
        xhi_base + (size_t)NN * CC, xlo_base + (size_t)NN * CC,
        whi_base + (size_t)CC * CC, wlo_base + (size_t)CC * CC, b_code, h_code,
        att_dst_rc, att_src_cr, a_dst_rc, a_src_cr);

    // ---- fused softmax + aggregation + relu + BN partials ----
    // rc: dst = code nodes, src = req;  cr: dst = req nodes, src = code
    agg_kernel<<<1184, 256>>>(off_rc, csr_rc, a_src_rc, a_dst_rc, h_req, out_code, bn_code);
    agg_kernel<<<1184, 256>>>(off_cr, csr_cr, a_src_cr, a_dst_cr, h_code, out_req, bn_req);

    // ---- batchnorm finalize ----
    bn_finalize_kernel<<<1, 256>>>(bn_req, gamma, beta, scale_req, shift_req);
    bn_finalize_kernel<<<1, 256>>>(bn_code, gamma, beta, scale_code, shift_code);

    // ---- edge classifier ----
    edge_predict_kernel<<<(EL * 32 + 255) / 256, 256>>>(
        li, lj, out_req, out_code, scale_req, shift_req, scale_code, shift_code, y);
}

// round 17
// speedup vs baseline: 1.9968x; 1.0387x over previous
#include <cuda_runtime.h>
#include <cuda_bf16.h>
#include <cuda_fp16.h>
#include <cstdint>

// Problem constants
constexpr int NN = 100000;   // N_REQ == N_CODE
constexpr int CC = 256;      // C_OUT == C_IN
constexpr int HH = 8;        // heads
constexpr int EE = 500000;   // edges per type
constexpr int EL = 200000;   // label edges
constexpr int SCAN_BS = 1024;
constexpr int SCAN_NB = (NN + SCAN_BS - 1) / SCAN_BS;   // 98

// ---------------- device scratch (static, no allocations) ----------------
__device__ __align__(16) __half    g_h[2][NN * CC];       // projected features (fp16)
__device__ __align__(16) __half    g_out[2][NN * CC];     // aggregated (relu'd, fp16)
__device__ __align__(16) float     g_a[4][NN * HH];       // attention scalars
__device__ __align__(16) float     g_bnstat[2][2 * CC];
__device__ __align__(16) float     g_scale[2][CC];
__device__ __align__(16) float     g_shift[2][CC];
// CSR build scratch
__device__ __align__(16) int       g_cnt[2][NN];
__device__ __align__(16) int       g_wptr[2][NN];
__device__ __align__(16) int       g_off[2][NN];
__device__ __align__(16) int       g_bsum[2][128];
__device__ __align__(16) int       g_auxex[2][128];
__device__ __align__(16) int       g_csr_src[2][EE];
// bf16 hi/lo split buffers for tensor-core GEMM
__device__ __align__(16) __nv_bfloat16 g_xhi[2][NN * CC];
__device__ __align__(16) __nv_bfloat16 g_xlo[2][NN * CC];
__device__ __align__(16) __nv_bfloat16 g_whi[2][CC * CC];
__device__ __align__(16) __nv_bfloat16 g_wlo[2][CC * CC];

// ---------------- PTX helpers (plain sm_80+ features only) ----------------
__device__ __forceinline__ uint32_t smem_to_u32(const void* p) {
    uint32_t a;
    asm("{ .reg .u64 t; cvta.to.shared.u64 t, %1; cvt.u32.u64 %0, t; }" : "=r"(a) : "l"(p));
    return a;
}
#define SMEM_SWIZZLE_128B(o) ((o) ^ (((o) >> 3) & 0x70))

__device__ __forceinline__ void cp16g(uint32_t dst, const void* src) {
    asm volatile("cp.async.cg.shared.global [%0], [%1], 16;" :: "r"(dst), "l"(src));
}
#define CP_COMMIT() asm volatile("cp.async.commit_group;" ::: "memory")
#define CP_WAIT1()  asm volatile("cp.async.wait_group 1;" ::: "memory")
#define CP_WAIT0()  asm volatile("cp.async.wait_group 0;" ::: "memory")

__device__ __forceinline__ void ldsm4(uint32_t* r, uint32_t addr) {
    asm volatile("ldmatrix.sync.aligned.m8n8.x4.shared.b16 {%0,%1,%2,%3}, [%4];"
        : "=r"(r[0]), "=r"(r[1]), "=r"(r[2]), "=r"(r[3]) : "r"(addr));
}

__device__ __forceinline__ void mma_bf16(float* c, const uint32_t* a, uint32_t b0, uint32_t b1) {
    asm volatile("mma.sync.aligned.m16n8k16.row.col.f32.bf16.bf16.f32 "
        "{%0,%1,%2,%3}, {%4,%5,%6,%7}, {%8,%9}, {%0,%1,%2,%3};"
        : "+f"(c[0]), "+f"(c[1]), "+f"(c[2]), "+f"(c[3])
        : "r"(a[0]), "r"(a[1]), "r"(a[2]), "r"(a[3]), "r"(b0), "r"(b1));
}

// ---------------- arg bundles ----------------
struct GemmArgs {
    const float* bias[2];
    const float* att1[2];
    const float* att2[2];
    float* a1[2];
    float* a2[2];
};
struct AggArgs {
    const int*    off[2];
    const int*    csr[2];
    const float*  a_s[2];
    const float*  a_d[2];
    const __half* h[2];
    __half*       out[2];
    float*        stat[2];
};

// ---------------- generic small kernels ----------------

__global__ void zero_kernel(float4* p, int n4) {
    int i = blockIdx.x * blockDim.x + threadIdx.x;
    int stride = gridDim.x * blockDim.x;
    float4 z = make_float4(0.f, 0.f, 0.f, 0.f);
    for (; i < n4; i += stride) p[i] = z;
}

// split fp32 -> bf16 hi + bf16 lo (exact residual split)
__global__ void split_kernel(const float4* __restrict__ x,
                             uint2* __restrict__ hi, uint2* __restrict__ lo, int n4) {
    int i = blockIdx.x * blockDim.x + threadIdx.x;
    if (i >= n4) return;
    float4 v = x[i];
    __nv_bfloat16 h0 = __float2bfloat16(v.x), h1 = __float2bfloat16(v.y);
    __nv_bfloat16 h2 = __float2bfloat16(v.z), h3 = __float2bfloat16(v.w);
    __nv_bfloat16 l0 = __float2bfloat16(v.x - __bfloat162float(h0));
    __nv_bfloat16 l1 = __float2bfloat16(v.y - __bfloat162float(h1));
    __nv_bfloat16 l2 = __float2bfloat16(v.z - __bfloat162float(h2));
    __nv_bfloat16 l3 = __float2bfloat16(v.w - __bfloat162float(h3));
    uint2 H, L;
    H.x = ((uint32_t)__bfloat16_as_ushort(h1) << 16) | __bfloat16_as_ushort(h0);
    H.y = ((uint32_t)__bfloat16_as_ushort(h3) << 16) | __bfloat16_as_ushort(h2);
    L.x = ((uint32_t)__bfloat16_as_ushort(l1) << 16) | __bfloat16_as_ushort(l0);
    L.y = ((uint32_t)__bfloat16_as_ushort(l3) << 16) | __bfloat16_as_ushort(l2);
    hi[i] = H;
    lo[i] = L;
}

// ---------------- CSR build (histogram + scan + fill) ----------------

__global__ void count_kernel(const int* __restrict__ dst, int* __restrict__ cnt) {
    int e = blockIdx.x * blockDim.x + threadIdx.x;
    if (e < EE) atomicAdd(&cnt[dst[e]], 1);
}

__global__ void blocksum_kernel(const int* __restrict__ cnt, int* __restrict__ bsum) {
    __shared__ int s[SCAN_BS];
    int i = blockIdx.x * SCAN_BS + threadIdx.x;
    s[threadIdx.x] = (i < NN) ? cnt[i] : 0;
    __syncthreads();
    for (int o = SCAN_BS / 2; o; o >>= 1) {
        if (threadIdx.x < o) s[threadIdx.x] += s[threadIdx.x + o];
        __syncthreads();
    }
    if (threadIdx.x == 0) bsum[blockIdx.x] = s[0];
}

__global__ void auxscan_kernel(const int* __restrict__ bsum, int* __restrict__ auxex) {
    __shared__ int s[128];
    int t = threadIdx.x;
    int v0 = (t < SCAN_NB) ? bsum[t] : 0;
    s[t] = v0;
    __syncthreads();
    for (int o = 1; o < 128; o <<= 1) {
        int v = (t >= o) ? s[t - o] : 0;
        __syncthreads();
        s[t] += v;
        __syncthreads();
    }
    if (t < SCAN_NB) auxex[t] = s[t] - v0;   // exclusive
}

__global__ void offsets_kernel(const int* __restrict__ cnt, const int* __restrict__ auxex,
                               int* __restrict__ off) {
    __shared__ int s[SCAN_BS];
    int i = blockIdx.x * SCAN_BS + threadIdx.x;
    int v0 = (i < NN) ? cnt[i] : 0;
    s[threadIdx.x] = v0;
    __syncthreads();
    for (int o = 1; o < SCAN_BS; o <<= 1) {
        int v = (threadIdx.x >= o) ? s[threadIdx.x - o] : 0;
        __syncthreads();
        s[threadIdx.x] += v;
        __syncthreads();
    }
    if (i < NN) off[i] = auxex[blockIdx.x] + s[threadIdx.x] - v0;  // exclusive
}

__global__ void fill_kernel(const int* __restrict__ src, const int* __restrict__ dst,
                            const int* __restrict__ off, int* __restrict__ wptr,
                            int* __restrict__ csr_src) {
    int e = blockIdx.x * blockDim.x + threadIdx.x;
    if (e >= EE) return;
    int d = dst[e];
    int pos = off[d] + atomicAdd(&wptr[d], 1);
    csr_src[pos] = src[e];
}

// ---------------- HMMA GEMM (bf16 hi/lo 3-term), full N=256 per CTA ----------------
// H[M=128/CTA, N=256] = Xhi*Whi^T + Xhi*Wlo^T + Xlo*Whi^T + bias.
// 512 threads = 16 warps: 2 (M, 64 rows) x 8 (N, 32 cols = one head each).
// blockIdx.y = node type. Fused epilogue: fp16 h store + per-head attention dots.
__global__ void __launch_bounds__(512, 1) mma_gemm_kernel(
    const __nv_bfloat16* __restrict__ xhi_b, const __nv_bfloat16* __restrict__ xlo_b,
    const __nv_bfloat16* __restrict__ whi_b, const __nv_bfloat16* __restrict__ wlo_b,
    __half* __restrict__ h_b, GemmArgs args)
{
    const int t = blockIdx.y;
    const __nv_bfloat16* xhi = xhi_b + (size_t)t * NN * CC;
    const __nv_bfloat16* xlo = xlo_b + (size_t)t * NN * CC;
    const __nv_bfloat16* whi = whi_b + (size_t)t * CC * CC;
    const __nv_bfloat16* wlo = wlo_b + (size_t)t * CC * CC;
    __half* Hout = h_b + (size_t)t * NN * CC;
    const float* bias = args.bias[t];
    const float* att1 = args.att1[t];
    const float* att2 = args.att2[t];
    float* a1 = args.a1[t];
    float* a2 = args.a2[t];

    extern __shared__ char dsm[];
    uint32_t sb = smem_to_u32(dsm);
    uint32_t abase = (sb + 1023) & ~1023u;
    uint32_t A_OFF[2] = {abase, abase + 16384};
    uint32_t B_OFF[2] = {abase + 32768, abase + 65536};

    const int tid = threadIdx.x;
    const int wid = tid >> 5;
    const int lane = tid & 31;
    const int wm = wid >> 3;        // 0..1 : 64-row half
    const int wn = wid & 7;         // 0..7 : 32-col group = head
    const int row0 = blockIdx.x * 128;

    float acc[4][4][4];
#pragma unroll
    for (int a = 0; a < 4; a++)
#pragma unroll
        for (int b = 0; b < 4; b++)
#pragma unroll
            for (int c = 0; c < 4; c++) acc[a][b][c] = 0.f;

    auto load_chunk = [&](int cc, int buf) {
        int piece = cc >> 2, kc = cc & 3;
        const char* Asrc = (const char*)((piece < 2) ? xhi : xlo);
        const char* Bsrc = (const char*)((piece == 1) ? wlo : whi);
#pragma unroll
        for (int j = 0; j < 2; j++) {    // A: 128 rows x 128B = 1024 segs
            int s = tid + j * 512;
            int r = s >> 3, o = s & 7;
            int gr = min(row0 + r, NN - 1);
            uint32_t dst = A_OFF[buf] + SMEM_SWIZZLE_128B(r * 128 + o * 16);
            cp16g(dst, Asrc + (size_t)gr * 512 + kc * 128 + o * 16);
        }
#pragma unroll
        for (int j = 0; j < 4; j++) {    // B: 256 n-rows x 128B = 2048 segs
            int s = tid + j * 512;
            int r = s >> 3, o = s & 7;
            uint32_t dst = B_OFF[buf] + SMEM_SWIZZLE_128B(r * 128 + o * 16);
            cp16g(dst, Bsrc + (size_t)r * 512 + kc * 128 + o * 16);
        }
    };

    const int a_r = wm * 64 + (lane & 15);
    const int a_blk = lane >> 4;
    const int b_r = wn * 32 + ((lane >> 4) & 1) * 8 + (lane & 7);
    const int b_blk = (lane >> 3) & 1;

    load_chunk(0, 0);
    CP_COMMIT();
    for (int cc = 0; cc < 12; cc++) {
        if (cc + 1 < 12) {
            load_chunk(cc + 1, (cc + 1) & 1);
            CP_COMMIT();
            CP_WAIT1();
        } else {
            CP_WAIT0();
        }
        __syncthreads();
        uint32_t Ab = A_OFF[cc & 1], Bb = B_OFF[cc & 1];
#pragma unroll
        for (int ks = 0; ks < 4; ks++) {
            uint32_t afr[4][4];
#pragma unroll
            for (int mt = 0; mt < 4; mt++) {
                int byte = (a_r + mt * 16) * 128 + (ks * 2 + a_blk) * 16;
                ldsm4(afr[mt], Ab + SMEM_SWIZZLE_128B(byte));
            }
            uint32_t bfr[2][4];
#pragma unroll
            for (int nt2 = 0; nt2 < 2; nt2++) {
                int byte = (b_r + nt2 * 16) * 128 + (ks * 2 + b_blk) * 16;
                ldsm4(bfr[nt2], Bb + SMEM_SWIZZLE_128B(byte));
            }
#pragma unroll
            for (int mt = 0; mt < 4; mt++)
#pragma unroll
                for (int nt = 0; nt < 4; nt++)
                    mma_bf16(acc[mt][nt], afr[mt],
                             bfr[nt >> 1][(nt & 1) * 2], bfr[nt >> 1][(nt & 1) * 2 + 1]);
        }
        __syncthreads();
    }

    const int head = wn;
    const int q = lane & 3;
#pragma unroll
    for (int mt = 0; mt < 4; mt++) {
        int r0g = row0 + wm * 64 + mt * 16 + (lane >> 2);
        int r1g = r0g + 8;
        float p1a = 0.f, p1b = 0.f, p2a = 0.f, p2b = 0.f;
#pragma unroll
        for (int nt = 0; nt < 4; nt++) {
            int col = wn * 32 + nt * 8 + q * 2;
            float bs0 = __ldg(&bias[col]), bs1 = __ldg(&bias[col + 1]);
            float v0 = acc[mt][nt][0] + bs0, v1 = acc[mt][nt][1] + bs1;
            float v2 = acc[mt][nt][2] + bs0, v3 = acc[mt][nt][3] + bs1;
            if (r0g < NN)
                *(__half2*)&Hout[(size_t)r0g * 256 + col] = __floats2half2_rn(v0, v1);
            if (r1g < NN)
                *(__half2*)&Hout[(size_t)r1g * 256 + col] = __floats2half2_rn(v2, v3);
            float t10 = __ldg(&att1[col]), t11 = __ldg(&att1[col + 1]);
            float t20 = __ldg(&att2[col]), t21 = __ldg(&att2[col + 1]);
            p1a += v0 * t10 + v1 * t11;  p1b += v2 * t10 + v3 * t11;
            p2a += v0 * t20 + v1 * t21;  p2b += v2 * t20 + v3 * t21;
        }
#pragma unroll
        for (int o = 1; o <= 2; o <<= 1) {
            p1a += __shfl_xor_sync(0xFFFFFFFFu, p1a, o);
            p1b += __shfl_xor_sync(0xFFFFFFFFu, p1b, o);
            p2a += __shfl_xor_sync(0xFFFFFFFFu, p2a, o);
            p2b += __shfl_xor_sync(0xFFFFFFFFu, p2b, o);
        }
        if (q == 0) {
            if (r0g < NN) { a1[r0g * 8 + head] = p1a; a2[r0g * 8 + head] = p2a; }
            if (r1g < NN) { a1[r1g * 8 + head] = p1b; a2[r1g * 8 + head] = p2b; }
        }
    }
}

// ---------------- fused softmax + aggregation + relu + BN partials ----------------
// One warp per dst node (persistent grid-stride on x; blockIdx.y = edge type).
// pass A: per-head max; pass B: unnormalized weighted sum; epilogue: relu,
// fp16 out write, per-warp smem BN partials -> global atomics once per CTA.
__global__ void __launch_bounds__(256) agg_kernel(AggArgs args)
{
    const int t = blockIdx.y;
    const int* __restrict__ off = args.off[t];
    const int* __restrict__ csr_src = args.csr[t];
    const float* __restrict__ a_s = args.a_s[t];
    const float* __restrict__ a_d = args.a_d[t];
    const __half* __restrict__ hsrc = args.h[t];
    __half* __restrict__ out = args.out[t];
    float* __restrict__ stat = args.stat[t];

    __shared__ float sm[8][512];   // per-warp [sum(256), sumsq(256)]
    const int tid = threadIdx.x;
    const int wid = tid >> 5;
    const int lane = tid & 31;
    const int h = lane & 7;
    const int myhead = lane >> 2;          // head of this lane's 8 columns

#pragma unroll
    for (int j = 0; j < 16; j++) sm[wid][lane + j * 32] = 0.f;
    __syncwarp();

    const int nwarps = gridDim.x * 8;
    for (int d = blockIdx.x * 8 + wid; d < NN; d += nwarps) {
        int beg = off[d];
        int end = (d == NN - 1) ? EE : off[d + 1];
        float ad = a_d[d * 8 + h];

        // pass A: per-head max (4 edges in parallel: sub = lane>>3)
        float mx = -1e30f;
        for (int i = beg + (lane >> 3); i < end; i += 4) {
            int s = csr_src[i];
            float v = a_s[s * 8 + h] + ad;
            v = v > 0.f ? v : 0.2f * v;
            mx = fmaxf(mx, v);
        }
        mx = fmaxf(mx, __shfl_xor_sync(0xFFFFFFFFu, mx, 8));
        mx = fmaxf(mx, __shfl_xor_sync(0xFFFFFFFFu, mx, 16));

        // pass B: accumulate unnormalized weighted sum
        float acc[8];
#pragma unroll
        for (int j = 0; j < 8; j++) acc[j] = 0.f;
        float wsum = 0.f;
        for (int i = beg; i < end; i++) {
            int s = csr_src[i];
            float v = a_s[s * 8 + h] + ad;
            v = v > 0.f ? v : 0.2f * v;
            float w = __expf(v - mx);
            wsum += w;
            float wh = __shfl_sync(0xFFFFFFFFu, w, myhead);
            uint4 raw = *(const uint4*)&hsrc[(size_t)s * 256 + lane * 8];
            __half2 p0 = *reinterpret_cast<__half2*>(&raw.x);
            __half2 p1 = *reinterpret_cast<__half2*>(&raw.y);
            __half2 p2 = *reinterpret_cast<__half2*>(&raw.z);
            __half2 p3 = *reinterpret_cast<__half2*>(&raw.w);
            float2 f0 = __half22float2(p0), f1 = __half22float2(p1);
            float2 f2 = __half22float2(p2), f3 = __half22float2(p3);
            acc[0] += f0.x * wh; acc[1] += f0.y * wh;
            acc[2] += f1.x * wh; acc[3] += f1.y * wh;
            acc[4] += f2.x * wh; acc[5] += f2.y * wh;
            acc[6] += f3.x * wh; acc[7] += f3.y * wh;
        }
        float ws = __shfl_sync(0xFFFFFFFFu, wsum, myhead);
        float inv = 1.f / (ws + 1e-16f);

        // relu + fp16 write + BN partials
        float ovals[8];
#pragma unroll
        for (int j = 0; j < 8; j++) {
            float val = fmaxf(acc[j] * inv, 0.f);
            ovals[j] = val;
            int c = lane * 8 + j;
            sm[wid][c] += val;
            sm[wid][256 + c] += val * val;
        }
        uint4 packed;
        __half2 q0 = __floats2half2_rn(ovals[0], ovals[1]);
        __half2 q1 = __floats2half2_rn(ovals[2], ovals[3]);
        __half2 q2 = __floats2half2_rn(ovals[4], ovals[5]);
        __half2 q3 = __floats2half2_rn(ovals[6], ovals[7]);
        packed.x = *reinterpret_cast<uint32_t*>(&q0);
        packed.y = *reinterpret_cast<uint32_t*>(&q1);
        packed.z = *reinterpret_cast<uint32_t*>(&q2);
        packed.w = *reinterpret_cast<uint32_t*>(&q3);
        *(uint4*)&out[(size_t)d * 256 + lane * 8] = packed;
    }

    __syncthreads();
    // reduce 8 warp regions -> global stat (512 atomics per CTA)
    for (int t2 = tid; t2 < 512; t2 += 256) {
        float s = 0.f;
#pragma unroll
        for (int w = 0; w < 8; w++) s += sm[w][t2];
        atomicAdd(&stat[t2], s);
    }
}

__global__ void bn_finalize_kernel(const float* __restrict__ stat,
                                   const float* __restrict__ gamma,
                                   const float* __restrict__ beta,
                                   float* __restrict__ scale, float* __restrict__ shift)
{
    int c = threadIdx.x;
    const float inv = 1.f / (float)NN;
    float mu = stat[c] * inv;
    float var = stat[256 + c] * inv - mu * mu;
    float sc = gamma[c] * rsqrtf(var + 1e-5f);
    scale[c] = sc;
    shift[c] = beta[c] - mu * sc;
}

// Final: per label edge dot of normalized fp16 features, sigmoid. One warp per edge.
__global__ void __launch_bounds__(256) edge_predict_kernel(
    const int* __restrict__ li, const int* __restrict__ lj,
    const __half* __restrict__ outr, const __half* __restrict__ outc,
    const float* __restrict__ scale_r, const float* __restrict__ shift_r,
    const float* __restrict__ scale_c, const float* __restrict__ shift_c,
    float* __restrict__ y)
{
    __shared__ float s_sr[256], s_hr[256], s_sc[256], s_hc[256];
    {
        int t = threadIdx.x;
        s_sr[t] = scale_r[t]; s_hr[t] = shift_r[t];
        s_sc[t] = scale_c[t]; s_hc[t] = shift_c[t];
    }
    __syncthreads();

    int warp = (blockIdx.x * blockDim.x + threadIdx.x) >> 5;
    int lane = threadIdx.x & 31;
    if (warp >= EL) return;
    int i = li[warp], j = lj[warp];
    uint4 rr = *(const uint4*)&outr[(size_t)i * 256 + lane * 8];
    uint4 rc = *(const uint4*)&outc[(size_t)j * 256 + lane * 8];
    const uint32_t* pr = &rr.x;
    const uint32_t* pc = &rc.x;
    float acc = 0.f;
#pragma unroll
    for (int p = 0; p < 4; p++) {
        float2 fr = __half22float2(*reinterpret_cast<const __half2*>(&pr[p]));
        float2 fc = __half22float2(*reinterpret_cast<const __half2*>(&pc[p]));
        int c0 = lane * 8 + p * 2;
        float zr0 = fr.x * s_sr[c0] + s_hr[c0];
        float zc0 = fc.x * s_sc[c0] + s_hc[c0];
        float zr1 = fr.y * s_sr[c0 + 1] + s_hr[c0 + 1];
        float zc1 = fc.y * s_sc[c0 + 1] + s_hc[c0 + 1];
        acc += zr0 * zc0 + zr1 * zc1;
    }
#pragma unroll
    for (int o = 16; o; o >>= 1) acc += __shfl_down_sync(0xFFFFFFFFu, acc, o);
    if (lane == 0) y[warp] = 1.f / (1.f + __expf(-acc));
}

// ---------------- host launch ----------------

extern "C" void kernel_launch(void* const* d_in, const int* in_sizes, int n_in,
                              void* d_out, int out_size)
{
    const float* x_req   = (const float*)d_in[0];
    const float* x_code  = (const float*)d_in[1];
    const int*   ei_rc   = (const int*)d_in[2];
    const int*   ei_cr   = (const int*)d_in[3];
    const int*   eli     = (const int*)d_in[4];
    const float* W_req   = (const float*)d_in[5];
    const float* b_req   = (const float*)d_in[6];
    const float* W_code  = (const float*)d_in[7];
    const float* b_code  = (const float*)d_in[8];
    const float* att_src_rc = (const float*)d_in[9];
    const float* att_dst_rc = (const float*)d_in[10];
    const float* att_src_cr = (const float*)d_in[11];
    const float* att_dst_cr = (const float*)d_in[12];
    // d_in[13..15]: k_W, k_b, q -> identity here (softmax over single metapath)
    const float* gamma = (const float*)d_in[16];
    const float* beta  = (const float*)d_in[17];
    float* y = (float*)d_out;

    float *a_base, *bn_base, *scale_base, *shift_base;
    int *cnt_base, *wptr_base, *off_base, *bsum_base, *auxex_base, *csr_base;
    __half *h_base, *out_base;
    __nv_bfloat16 *xhi_base, *xlo_base, *whi_base, *wlo_base;
    cudaGetSymbolAddress((void**)&h_base, g_h);
    cudaGetSymbolAddress((void**)&out_base, g_out);
    cudaGetSymbolAddress((void**)&a_base, g_a);
    cudaGetSymbolAddress((void**)&bn_base, g_bnstat);
    cudaGetSymbolAddress((void**)&scale_base, g_scale);
    cudaGetSymbolAddress((void**)&shift_base, g_shift);
    cudaGetSymbolAddress((void**)&cnt_base, g_cnt);
    cudaGetSymbolAddress((void**)&wptr_base, g_wptr);
    cudaGetSymbolAddress((void**)&off_base, g_off);
    cudaGetSymbolAddress((void**)&bsum_base, g_bsum);
    cudaGetSymbolAddress((void**)&auxex_base, g_auxex);
    cudaGetSymbolAddress((void**)&csr_base, g_csr_src);
    cudaGetSymbolAddress((void**)&xhi_base, g_xhi);
    cudaGetSymbolAddress((void**)&xlo_base, g_xlo);
    cudaGetSymbolAddress((void**)&whi_base, g_whi);
    cudaGetSymbolAddress((void**)&wlo_base, g_wlo);

    __half* h_req  = h_base;
    __half* h_code = h_base + (size_t)NN * CC;
    __half* out_req  = out_base;
    __half* out_code = out_base + (size_t)NN * CC;
    float* a_src_rc = a_base + 0 * (size_t)NN * HH;
    float* a_dst_rc = a_base + 1 * (size_t)NN * HH;
    float* a_src_cr = a_base + 2 * (size_t)NN * HH;
    float* a_dst_cr = a_base + 3 * (size_t)NN * HH;
    float* bn_req  = bn_base;
    float* bn_code = bn_base + 2 * CC;
    float* scale_req  = scale_base;
    float* scale_code = scale_base + CC;
    float* shift_req  = shift_base;
    float* shift_code = shift_base + CC;

    const int* src_rc = ei_rc;          const int* dst_rc = ei_rc + EE;
    const int* src_cr = ei_cr;          const int* dst_cr = ei_cr + EE;
    const int* li = eli;                const int* lj = eli + EL;

    int* cnt_rc  = cnt_base;            int* cnt_cr  = cnt_base + NN;
    int* wptr_rc = wptr_base;           int* wptr_cr = wptr_base + NN;
    int* off_rc  = off_base;            int* off_cr  = off_base + NN;
    int* bsum_rc = bsum_base;           int* bsum_cr = bsum_base + 128;
    int* aux_rc  = auxex_base;          int* aux_cr  = auxex_base + 128;
    int* csr_rc  = csr_base;            int* csr_cr  = csr_base + EE;

    // ---- zero small scratch ----
    zero_kernel<<<128, 256>>>((float4*)cnt_base, (2 * NN) / 4);
    zero_kernel<<<128, 256>>>((float4*)wptr_base, (2 * NN) / 4);
    zero_kernel<<<1, 256>>>((float4*)bn_base, (2 * 2 * CC) / 4);

    // ---- CSR build (both edge types) ----
    int eg = (EE + 255) / 256;
    count_kernel<<<eg, 256>>>(dst_rc, cnt_rc);
    count_kernel<<<eg, 256>>>(dst_cr, cnt_cr);
    blocksum_kernel<<<SCAN_NB, SCAN_BS>>>(cnt_rc, bsum_rc);
    blocksum_kernel<<<SCAN_NB, SCAN_BS>>>(cnt_cr, bsum_cr);
    auxscan_kernel<<<1, 128>>>(bsum_rc, aux_rc);
    auxscan_kernel<<<1, 128>>>(bsum_cr, aux_cr);
    offsets_kernel<<<SCAN_NB, SCAN_BS>>>(cnt_rc, aux_rc, off_rc);
    offsets_kernel<<<SCAN_NB, SCAN_BS>>>(cnt_cr, aux_cr, off_cr);
    fill_kernel<<<eg, 256>>>(src_rc, dst_rc, off_rc, wptr_rc, csr_rc);
    fill_kernel<<<eg, 256>>>(src_cr, dst_cr, off_cr, wptr_cr, csr_cr);

    // ---- bf16 hi/lo splits ----
    {
        int n4x = NN * CC / 4;
        int gx = (n4x + 255) / 256;
        split_kernel<<<gx, 256>>>((const float4*)x_req,
            (uint2*)(xhi_base), (uint2*)(xlo_base), n4x);
        split_kernel<<<gx, 256>>>((const float4*)x_code,
            (uint2*)(xhi_base + (size_t)NN * CC), (uint2*)(xlo_base + (size_t)NN * CC), n4x);
        int n4w = CC * CC / 4;
        int gw = (n4w + 255) / 256;
        split_kernel<<<gw, 256>>>((const float4*)W_req,
            (uint2*)(whi_base), (uint2*)(wlo_base), n4w);
        split_kernel<<<gw, 256>>>((const float4*)W_code,
            (uint2*)(whi_base + (size_t)CC * CC), (uint2*)(wlo_base + (size_t)CC * CC), n4w);
    }

    // ---- HMMA GEMM: both types in one launch (blockIdx.y) ----
    GemmArgs ga;
    ga.bias[0] = b_req;      ga.bias[1] = b_code;
    ga.att1[0] = att_src_rc; ga.att1[1] = att_dst_rc;
    ga.att2[0] = att_dst_cr; ga.att2[1] = att_src_cr;
    ga.a1[0] = a_src_rc;     ga.a1[1] = a_dst_rc;
    ga.a2[0] = a_dst_cr;     ga.a2[1] = a_src_cr;
    const int SMEM_GEMM = 1024 + 2 * 16384 + 2 * 32768;  // 97 KB
    cudaFuncSetAttribute(mma_gemm_kernel, cudaFuncAttributeMaxDynamicSharedMemorySize, SMEM_GEMM);
    dim3 gg((NN + 127) / 128, 2);
    mma_gemm_kernel<<<gg, 512, SMEM_GEMM>>>(xhi_base, xlo_base, whi_base, wlo_base, h_base, ga);

    // ---- fused softmax + aggregation + relu + BN partials (both types) ----
    // t=0 (rc): dst=code, src=req;  t=1 (cr): dst=req, src=code
    AggArgs aa;
    aa.off[0] = off_rc;    aa.off[1] = off_cr;
    aa.csr[0] = csr_rc;    aa.csr[1] = csr_cr;
    aa.a_s[0] = a_src_rc;  aa.a_s[1] = a_src_cr;
    aa.a_d[0] = a_dst_rc;  aa.a_d[1] = a_dst_cr;
    aa.h[0]   = h_req;     aa.h[1]   = h_code;
    aa.out[0] = out_code;  aa.out[1] = out_req;
    aa.stat[0] = bn_code;  aa.stat[1] = bn_req;
    agg_kernel<<<dim3(1184, 2), 256>>>(aa);

    // ---- batchnorm finalize ----
    bn_finalize_kernel<<<1, 256>>>(bn_req, gamma, beta, scale_req, shift_req);
    bn_finalize_kernel<<<1, 256>>>(bn_code, gamma, beta, scale_code, shift_code);

    // ---- edge classifier ----
    edge_predict_kernel<<<(EL * 32 + 255) / 256, 256>>>(
        li, lj, out_req, out_code, scale_req, shift_req, scale_code, shift_code, y);
}